// round 1
// baseline (speedup 1.0000x reference)
#include <cuda_runtime.h>
#include <math.h>

// Problem constants
#define BB   4
#define TT   2048
#define NE   2048      // n_embd = K dim
#define DHH  128
#define NKVH 4
#define MROWS (BB*TT)  // 8192
#define NRED  1152     // 128 (q_sum) + 512 (K) + 512 (V)
#define KDIM  2048

// Scratch (device globals: allocation-free per harness rules)
__device__ float g_Wq[128 * KDIM];                 // summed Q weight  [128][2048]
__device__ float g_bred[NRED];                     // reduced bias
__device__ float g_qsum[MROWS * DHH];              // [B*T][128]
__device__ float g_k[BB * NKVH * TT * DHH];        // [B*KV][T][128]
__device__ float g_v[BB * NKVH * TT * DHH];        // [B*KV][T][128]

// ---------------------------------------------------------------------------
// Kernel A: build summed Q weight + reduced bias
// ---------------------------------------------------------------------------
__global__ void prep_kernel(const float* __restrict__ W, const float* __restrict__ b) {
    int idx = blockIdx.x * 256 + threadIdx.x;
    if (idx < 128 * KDIM) {
        int d = idx >> 11;          // 0..127
        int c = idx & (KDIM - 1);   // 0..2047
        float s = 0.f;
#pragma unroll
        for (int h = 0; h < 16; h++)
            s += W[(size_t)(h * 128 + d) * KDIM + c];
        g_Wq[idx] = s;
    }
    if (idx < NRED) {
        float v;
        if (idx < 128) {
            v = 0.f;
#pragma unroll
            for (int h = 0; h < 16; h++) v += b[h * 128 + idx];
        } else {
            v = b[idx + 1920];      // k rows: 2048+(n-128) = n+1920; v rows: 2560+(n-640) = n+1920
        }
        g_bred[idx] = v;
    }
}

// ---------------------------------------------------------------------------
// Kernel B: SGEMM  C[m][n] = sum_k x[m][k] * Wsrc(n)[k] + bias(n)
// M=8192, N=1152, K=2048.  BM=BN=128, BK=16, 256 threads, 8x8 micro-tiles.
// Scatters results into g_qsum / g_k / g_v (attention-friendly layouts).
// ---------------------------------------------------------------------------
__global__ void qkv_gemm(const float* __restrict__ x, const float* __restrict__ W) {
    __shared__ float As[16][132];   // [k][m]
    __shared__ float Bs[16][132];   // [k][n]

    const int tid = threadIdx.x;
    const int tx = tid & 15;        // n micro-tile
    const int ty = tid >> 4;        // m micro-tile
    const int m0 = blockIdx.y * 128;
    const int n0 = blockIdx.x * 128;

    float acc[8][8];
#pragma unroll
    for (int i = 0; i < 8; i++)
#pragma unroll
        for (int j = 0; j < 8; j++) acc[i][j] = 0.f;

    for (int k0 = 0; k0 < KDIM; k0 += 16) {
        // Load A tile: 128x16, transposed into As[k][m]
#pragma unroll
        for (int p = 0; p < 2; p++) {
            int f4 = tid + 256 * p;
            int row = f4 >> 2;      // 0..127
            int c4  = f4 & 3;       // 0..3
            float4 a = *(const float4*)(x + (size_t)(m0 + row) * KDIM + k0 + c4 * 4);
            As[c4 * 4 + 0][row] = a.x;
            As[c4 * 4 + 1][row] = a.y;
            As[c4 * 4 + 2][row] = a.z;
            As[c4 * 4 + 3][row] = a.w;
        }
        // Load B tile with row remap (n<128 -> summed Q weight, else raw W row n+1920)
#pragma unroll
        for (int p = 0; p < 2; p++) {
            int f4 = tid + 256 * p;
            int row = f4 >> 2;
            int c4  = f4 & 3;
            int n = n0 + row;
            const float* wsrc = (n < 128) ? (g_Wq + (size_t)n * KDIM)
                                          : (W + (size_t)(n + 1920) * KDIM);
            float4 bv = *(const float4*)(wsrc + k0 + c4 * 4);
            Bs[c4 * 4 + 0][row] = bv.x;
            Bs[c4 * 4 + 1][row] = bv.y;
            Bs[c4 * 4 + 2][row] = bv.z;
            Bs[c4 * 4 + 3][row] = bv.w;
        }
        __syncthreads();

#pragma unroll
        for (int kk = 0; kk < 16; kk++) {
            float a[8], bb[8];
            *(float4*)(a)      = *(const float4*)&As[kk][ty * 8];
            *(float4*)(a + 4)  = *(const float4*)&As[kk][ty * 8 + 4];
            *(float4*)(bb)     = *(const float4*)&Bs[kk][tx * 8];
            *(float4*)(bb + 4) = *(const float4*)&Bs[kk][tx * 8 + 4];
#pragma unroll
            for (int i = 0; i < 8; i++)
#pragma unroll
                for (int j = 0; j < 8; j++)
                    acc[i][j] += a[i] * bb[j];
        }
        __syncthreads();
    }

    // Epilogue: bias + scatter. Each 128-wide col tile falls entirely in one region.
    const int nloc = n0 + tx * 8;
    float bias[8];
#pragma unroll
    for (int j = 0; j < 8; j++) bias[j] = g_bred[nloc + j];

    const int region = (n0 == 0) ? 0 : (n0 < 640 ? 1 : 2);

#pragma unroll
    for (int i = 0; i < 8; i++) {
        int m = m0 + ty * 8 + i;
        int bidx = m >> 11;          // / 2048
        int t    = m & (TT - 1);
        float v0 = acc[i][0] + bias[0], v1 = acc[i][1] + bias[1];
        float v2 = acc[i][2] + bias[2], v3 = acc[i][3] + bias[3];
        float v4 = acc[i][4] + bias[4], v5 = acc[i][5] + bias[5];
        float v6 = acc[i][6] + bias[6], v7 = acc[i][7] + bias[7];
        float* dst;
        if (region == 0) {
            dst = g_qsum + (size_t)m * 128 + nloc;
        } else if (region == 1) {
            int i2 = nloc - 128;
            int kvh = i2 >> 7, d = i2 & 127;
            dst = g_k + ((size_t)((bidx << 2) + kvh) * TT + t) * 128 + d;
        } else {
            int i2 = nloc - 640;
            int kvh = i2 >> 7, d = i2 & 127;
            dst = g_v + ((size_t)((bidx << 2) + kvh) * TT + t) * 128 + d;
        }
        *(float4*)(dst)     = make_float4(v0, v1, v2, v3);
        *(float4*)(dst + 4) = make_float4(v4, v5, v6, v7);
    }
}

// ---------------------------------------------------------------------------
// Kernel C: flash attention.  Block = (b,kv, 16-query tile), 128 threads.
// KV tiles of 128. Online softmax. smem rows padded to 132 floats.
// ---------------------------------------------------------------------------
#define ATTN_SMEM_FLOATS 38016   // 2048 + 16896 + 16896 + 2048 + 64 + 4*16
#define ATTN_SMEM_BYTES  (ATTN_SMEM_FLOATS * 4)

__global__ void attn_kernel(float* __restrict__ out) {
    extern __shared__ __align__(16) float sm[];
    float* Qs     = sm;                  // [16][128]
    float* Ks     = sm + 2048;           // [128][132]
    float* Vs     = Ks + 128 * 132;      // [128][132]
    float* Ps     = Vs + 128 * 132;      // [16][128]
    float* red    = Ps + 2048;           // [4][16]
    float* mstate = red + 64;            // [16]
    float* lstate = mstate + 16;         // [16]
    float* alpha  = lstate + 16;         // [16]
    float* mcur   = alpha + 16;          // [16]

    const int tid  = threadIdx.x;
    const int lane = tid & 31;
    const int warp = tid >> 5;
    const int bh   = blockIdx.y;         // b*4 + kv
    const int b    = bh >> 2;
    const int kv   = bh & 3;
    const int q0   = blockIdx.x * 16;
    const float scale = 0.08838834764831845f;   // 1/sqrt(128)

    // Load Q tile, pre-scaled
    const float* qbase = g_qsum + (size_t)(b * TT + q0) * DHH;
#pragma unroll
    for (int f4 = tid, it = 0; it < 4; it++, f4 += 128) {
        int r = f4 >> 5, c4 = f4 & 31;
        float4 q = *(const float4*)(qbase + r * DHH + c4 * 4);
        q.x *= scale; q.y *= scale; q.z *= scale; q.w *= scale;
        *(float4*)(Qs + r * 128 + c4 * 4) = q;
    }
    if (tid < 16) { mstate[tid] = -INFINITY; lstate[tid] = 0.f; }

    float4 O[4];
#pragma unroll
    for (int ii = 0; ii < 4; ii++) O[ii] = make_float4(0.f, 0.f, 0.f, 0.f);
    const int igrp = warp;   // 4 queries per warp in PV phase
    const int d4   = lane;   // float4 column in PV phase

    const float* kb = g_k + (size_t)bh * TT * DHH;
    const float* vb = g_v + (size_t)bh * TT * DHH;

    for (int kt = 0; kt < TT; kt += 128) {
        __syncthreads();   // protect Ks/Vs from previous iteration consumers
        // Load K/V tiles (coalesced, one warp per gmem row)
#pragma unroll 4
        for (int p = 0; p < 32; p++) {
            int f = tid + p * 128;
            int r = f >> 5, c4 = f & 31;
            float4 kk = *(const float4*)(kb + (size_t)(kt + r) * DHH + c4 * 4);
            *(float4*)(Ks + r * 132 + c4 * 4) = kk;
            float4 vv = *(const float4*)(vb + (size_t)(kt + r) * DHH + c4 * 4);
            *(float4*)(Vs + r * 132 + c4 * 4) = vv;
        }
        __syncthreads();

        // --- S = Q . K^T : thread = key j = tid, acc over 16 queries ---
        float acc[16];
#pragma unroll
        for (int i = 0; i < 16; i++) acc[i] = 0.f;
        {
            const float* krow = Ks + tid * 132;
#pragma unroll 4
            for (int d4i = 0; d4i < 32; d4i++) {
                float4 k4 = *(const float4*)(krow + d4i * 4);
#pragma unroll
                for (int i = 0; i < 16; i++) {
                    float4 q4 = *(const float4*)(Qs + i * 128 + d4i * 4);
                    acc[i] += k4.x * q4.x + k4.y * q4.y + k4.z * q4.z + k4.w * q4.w;
                }
            }
        }

        // --- row max (warp reduce, then cross-warp via smem) ---
#pragma unroll
        for (int i = 0; i < 16; i++) {
            float m = acc[i];
#pragma unroll
            for (int off = 16; off; off >>= 1)
                m = fmaxf(m, __shfl_xor_sync(0xffffffffu, m, off));
            if (lane == 0) red[warp * 16 + i] = m;
        }
        __syncthreads();
        if (tid < 16) {
            float tmax = fmaxf(fmaxf(red[tid], red[16 + tid]),
                               fmaxf(red[32 + tid], red[48 + tid]));
            float mold = mstate[tid];
            float mnew = fmaxf(mold, tmax);
            mstate[tid] = mnew;
            mcur[tid]   = mnew;
            alpha[tid]  = __expf(mold - mnew);   // exp(-inf)=0 on first tile
        }
        __syncthreads();

        // --- P = exp(S - m), write to smem, row-sum ---
#pragma unroll
        for (int i = 0; i < 16; i++) {
            float p = __expf(acc[i] - mcur[i]);
            Ps[i * 128 + tid] = p;
#pragma unroll
            for (int off = 16; off; off >>= 1)
                p += __shfl_xor_sync(0xffffffffu, p, off);
            if (lane == 0) red[warp * 16 + i] = p;
        }
        __syncthreads();
        if (tid < 16) {
            lstate[tid] = lstate[tid] * alpha[tid] +
                          (red[tid] + red[16 + tid] + red[32 + tid] + red[48 + tid]);
        }

        // --- O = O*alpha + P.V : thread = (query group igrp, d4 column) ---
#pragma unroll
        for (int ii = 0; ii < 4; ii++) {
            float a = alpha[igrp * 4 + ii];
            O[ii].x *= a; O[ii].y *= a; O[ii].z *= a; O[ii].w *= a;
        }
#pragma unroll 4
        for (int j = 0; j < 128; j++) {
            float4 v4 = *(const float4*)(Vs + j * 132 + d4 * 4);
#pragma unroll
            for (int ii = 0; ii < 4; ii++) {
                float p = Ps[(igrp * 4 + ii) * 128 + j];
                O[ii].x += p * v4.x; O[ii].y += p * v4.y;
                O[ii].z += p * v4.z; O[ii].w += p * v4.w;
            }
        }
    }
    __syncthreads();   // make final lstate visible

    // Epilogue: normalize and store  out[b][t][kv*128 + d]
#pragma unroll
    for (int ii = 0; ii < 4; ii++) {
        int i = igrp * 4 + ii;
        float inv = 1.f / lstate[i];
        float4 o = O[ii];
        o.x *= inv; o.y *= inv; o.z *= inv; o.w *= inv;
        *(float4*)(out + (size_t)(b * TT + q0 + i) * 512 + kv * 128 + d4 * 4) = o;
    }
}

// ---------------------------------------------------------------------------
extern "C" void kernel_launch(void* const* d_in, const int* in_sizes, int n_in,
                              void* d_out, int out_size) {
    (void)in_sizes; (void)n_in; (void)out_size;
    const float* x = (const float*)d_in[0];   // [4,2048,2048]
    const float* W = (const float*)d_in[1];   // [3072,2048]
    const float* b = (const float*)d_in[2];   // [3072]
    float* out = (float*)d_out;               // [4,2048,512]

    cudaFuncSetAttribute(attn_kernel,
                         cudaFuncAttributeMaxDynamicSharedMemorySize,
                         ATTN_SMEM_BYTES);

    prep_kernel<<<1024, 256>>>(W, b);
    qkv_gemm<<<dim3(9, 64), 256>>>(x, W);
    attn_kernel<<<dim3(TT / 16, BB * NKVH), 128, ATTN_SMEM_BYTES>>>(out);
}

// round 2
// speedup vs baseline: 3.2770x; 3.2770x over previous
#include <cuda_runtime.h>
#include <cuda_bf16.h>
#include <math.h>

typedef __nv_bfloat16 bf16;

#define TT    2048
#define KDIM  2048
#define DH    128
#define NREDC 1152      // 128 q_sum + 512 K + 512 V
#define MROWS 8192
#define NBH   16
#define SCALE 0.08838834764831845f   // 1/sqrt(128)

// ---------------- device scratch (allocation-free) ----------------
__device__ bf16  g_xhi[(size_t)MROWS*KDIM];
__device__ bf16  g_xlo[(size_t)MROWS*KDIM];
__device__ bf16  g_whi[(size_t)NREDC*KDIM];
__device__ bf16  g_wlo[(size_t)NREDC*KDIM];
__device__ float g_bred[NREDC];
__device__ bf16  g_qhi[(size_t)MROWS*DH];
__device__ bf16  g_qlo[(size_t)MROWS*DH];
__device__ bf16  g_khi[(size_t)NBH*TT*DH];
__device__ bf16  g_klo[(size_t)NBH*TT*DH];
__device__ bf16  g_vthi[(size_t)NBH*DH*TT];   // V transposed [bh][d][t]
__device__ bf16  g_vtlo[(size_t)NBH*DH*TT];
__device__ float g_S  [(size_t)NBH*TT*TT];
__device__ bf16  g_phi[(size_t)NBH*TT*TT];
__device__ bf16  g_plo[(size_t)NBH*TT*TT];

// ---------------- helpers ----------------
__device__ __forceinline__ void split2(float v, bf16& h, bf16& l) {
    h = __float2bfloat16(v);
    l = __float2bfloat16(v - __bfloat162float(h));
}

__device__ __forceinline__ void cp16(void* sp, const void* gp) {
    unsigned s = (unsigned)__cvta_generic_to_shared(sp);
    asm volatile("cp.async.cg.shared.global [%0], [%1], 16;\n" :: "r"(s), "l"(gp));
}

#define LDSM4(R, addr) \
    asm volatile("ldmatrix.sync.aligned.m8n8.x4.shared.b16 {%0,%1,%2,%3}, [%4];" \
        : "=r"((R)[0]), "=r"((R)[1]), "=r"((R)[2]), "=r"((R)[3]) : "r"(addr))

#define MMA16816(C, A, b0, b1) \
    asm volatile("mma.sync.aligned.m16n8k16.row.col.f32.bf16.bf16.f32 " \
        "{%0,%1,%2,%3},{%4,%5,%6,%7},{%8,%9},{%0,%1,%2,%3};" \
        : "+f"((C)[0]), "+f"((C)[1]), "+f"((C)[2]), "+f"((C)[3]) \
        : "r"((A)[0]), "r"((A)[1]), "r"((A)[2]), "r"((A)[3]), "r"(b0), "r"(b1))

// ---------------- prep kernels ----------------
__global__ void prep_x(const float* __restrict__ x) {
    size_t i = ((size_t)blockIdx.x * 256 + threadIdx.x) * 4;
    float4 a = *(const float4*)(x + i);
    float arr[4] = {a.x, a.y, a.z, a.w};
#pragma unroll
    for (int j = 0; j < 4; j++) {
        bf16 h, l; split2(arr[j], h, l);
        g_xhi[i + j] = h;  g_xlo[i + j] = l;
    }
}

__global__ void prep_w(const float* __restrict__ W, const float* __restrict__ b) {
    int idx = blockIdx.x * 256 + threadIdx.x;   // < 1152*2048
    int n = idx >> 11, c = idx & 2047;
    float v;
    if (n < 128) {
        v = 0.f;
#pragma unroll
        for (int h = 0; h < 16; h++) v += W[(size_t)(h * 128 + n) * KDIM + c];
        v *= SCALE;                             // fold 1/sqrt(dh) into summed Q weight
    } else {
        v = W[(size_t)(n + 1920) * KDIM + c];   // K rows 2048.., V rows 2560..
    }
    bf16 hh, ll; split2(v, hh, ll);
    g_whi[idx] = hh;  g_wlo[idx] = ll;

    if (idx < NREDC) {
        float bv;
        if (idx < 128) {
            bv = 0.f;
#pragma unroll
            for (int h = 0; h < 16; h++) bv += b[h * 128 + idx];
            bv *= SCALE;
        } else bv = b[idx + 1920];
        g_bred[idx] = bv;
    }
}

// ---------------- projection epilogue scatter ----------------
__device__ __forceinline__ void proj_store(int m, int n, float v0, float v1) {
    bf16 h0, l0, h1, l1;
    split2(v0, h0, l0);  split2(v1, h1, l1);
    if (n < 128) {                       // q_sum  [m][128]
        size_t i = (size_t)m * DH + n;
        *(__nv_bfloat162*)&g_qhi[i] = __halves2bfloat162(h0, h1);
        *(__nv_bfloat162*)&g_qlo[i] = __halves2bfloat162(l0, l1);
    } else if (n < 640) {                // K  [bh][t][d]
        int i2 = n - 128;
        int bh = ((m >> 11) << 2) + (i2 >> 7);
        size_t i = (size_t)bh * TT * DH + (size_t)(m & 2047) * DH + (i2 & 127);
        *(__nv_bfloat162*)&g_khi[i] = __halves2bfloat162(h0, h1);
        *(__nv_bfloat162*)&g_klo[i] = __halves2bfloat162(l0, l1);
    } else {                             // V^T  [bh][d][t]
        int i2 = n - 640;
        int bh = ((m >> 11) << 2) + (i2 >> 7);
        int d  = i2 & 127;
        size_t i = (size_t)bh * DH * TT + (size_t)d * TT + (m & 2047);
        g_vthi[i] = h0;  g_vthi[i + TT] = h1;
        g_vtlo[i] = l0;  g_vtlo[i + TT] = l1;
    }
}

// ---------------- unified 3-pass split-bf16 GEMM ----------------
// C[m][n] = sum_k (Ahi+Alo)[m][k] * (Bhi+Blo)[n][k]   (3 passes: hh, hl, lh)
// Block tile 128x128, k-tile 32, 8 warps (64x32 warp tiles), cp.async 2-stage.
template<int MODE>
__global__ __launch_bounds__(256)
void gemm3(float* __restrict__ outp) {
    __shared__ bf16 sA[2][128 * 40];
    __shared__ bf16 sB[2][128 * 40];

    const int tid  = threadIdx.x;
    const int lane = tid & 31;
    const int warp = tid >> 5;
    const int wm   = warp >> 2;       // 0..1
    const int wn   = warp & 3;        // 0..3
    const int m0   = blockIdx.y * 128;
    const int n0   = blockIdx.x * 128;
    const int z    = blockIdx.z;

    const bf16 *Ah, *Al, *Bh, *Bl;
    float* Cp = nullptr;
    int Kc, lda, ldb, ldc_;
    if (MODE == 0) {
        Ah = g_xhi; Al = g_xlo; Bh = g_whi; Bl = g_wlo;
        Kc = KDIM; lda = KDIM; ldb = KDIM; ldc_ = 0;
    } else if (MODE == 1) {
        size_t ao = (size_t)(z >> 2) * TT * DH, bo = (size_t)z * TT * DH;
        Ah = g_qhi + ao; Al = g_qlo + ao; Bh = g_khi + bo; Bl = g_klo + bo;
        Cp = g_S + (size_t)z * TT * TT;
        Kc = DH; lda = DH; ldb = DH; ldc_ = TT;
    } else {
        size_t ao = (size_t)z * TT * TT, bo = (size_t)z * DH * TT;
        Ah = g_phi + ao; Al = g_plo + ao; Bh = g_vthi + bo; Bl = g_vtlo + bo;
        Cp = outp + (size_t)(z >> 2) * TT * 512 + (size_t)(z & 3) * DH;
        Kc = KDIM; lda = KDIM; ldb = KDIM; ldc_ = 512;
    }

    const bf16* Apass[3] = {Ah, Ah, Al};
    const bf16* Bpass[3] = {Bh, Bl, Bh};
    const int KT = Kc / 32;
    const int NT = 3 * KT;

    float acc[4][4][4];
#pragma unroll
    for (int mi = 0; mi < 4; mi++)
#pragma unroll
        for (int ni = 0; ni < 4; ni++)
#pragma unroll
            for (int r = 0; r < 4; r++) acc[mi][ni][r] = 0.f;

#define LOAD_TILE(t, bufi) do {                                              \
    int pass_ = (t) / KT;  int kk_ = ((t) % KT) * 32;                        \
    const bf16* A_ = Apass[pass_];  const bf16* B_ = Bpass[pass_];           \
    _Pragma("unroll")                                                        \
    for (int p = 0; p < 2; p++) {                                            \
        int cch = tid + (p << 8);                                            \
        int row = cch >> 2;  int col = (cch & 3) << 3;                       \
        cp16(&sA[bufi][row * 40 + col], A_ + (size_t)(m0 + row) * lda + kk_ + col); \
        cp16(&sB[bufi][row * 40 + col], B_ + (size_t)(n0 + row) * ldb + kk_ + col); \
    }                                                                        \
} while (0)

    LOAD_TILE(0, 0);
    asm volatile("cp.async.commit_group;\n");

    for (int kt = 0; kt < NT; kt++) {
        if (kt + 1 < NT) {
            LOAD_TILE(kt + 1, (kt + 1) & 1);
            asm volatile("cp.async.commit_group;\n");
            asm volatile("cp.async.wait_group 1;\n");
        } else {
            asm volatile("cp.async.wait_group 0;\n");
        }
        __syncthreads();

        const bf16* As = sA[kt & 1];
        const bf16* Bs = sB[kt & 1];
#pragma unroll
        for (int ks = 0; ks < 32; ks += 16) {
            unsigned af[4][4], bq[2][4];
#pragma unroll
            for (int mi = 0; mi < 4; mi++) {
                const bf16* p = As + (wm * 64 + mi * 16 + (lane & 15)) * 40
                                   + ks + ((lane >> 4) << 3);
                unsigned ad = (unsigned)__cvta_generic_to_shared(p);
                LDSM4(af[mi], ad);
            }
#pragma unroll
            for (int bi = 0; bi < 2; bi++) {
                const bf16* p = Bs + (wn * 32 + bi * 16 + (lane & 15)) * 40
                                   + ks + ((lane >> 4) << 3);
                unsigned ad = (unsigned)__cvta_generic_to_shared(p);
                LDSM4(bq[bi], ad);
            }
#pragma unroll
            for (int mi = 0; mi < 4; mi++)
#pragma unroll
                for (int ni = 0; ni < 4; ni++)
                    MMA16816(acc[mi][ni], af[mi], bq[ni >> 1][ni & 1], bq[ni >> 1][(ni & 1) + 2]);
        }
        __syncthreads();
    }
#undef LOAD_TILE

    // epilogue
#pragma unroll
    for (int mi = 0; mi < 4; mi++)
#pragma unroll
        for (int ni = 0; ni < 4; ni++) {
            int mr = m0 + wm * 64 + mi * 16 + (lane >> 2);
            int nc = n0 + wn * 32 + ni * 8 + ((lane & 3) << 1);
            float* c = acc[mi][ni];
            if (MODE == 0) {
                float b0v = g_bred[nc], b1v = g_bred[nc + 1];
                proj_store(mr,     nc, c[0] + b0v, c[1] + b1v);
                proj_store(mr + 8, nc, c[2] + b0v, c[3] + b1v);
            } else {
                *(float2*)(Cp + (size_t)mr * ldc_ + nc)       = make_float2(c[0], c[1]);
                *(float2*)(Cp + (size_t)(mr + 8) * ldc_ + nc) = make_float2(c[2], c[3]);
            }
        }
}

// ---------------- softmax over S rows, emits split P ----------------
__global__ void softmax_k() {
    size_t row = blockIdx.x;                    // 0..NBH*TT-1
    const float* s = g_S + row * (size_t)TT;
    int tid = threadIdx.x, lane = tid & 31, warp = tid >> 5;

    float v[8];
    float mx = -1e30f;
#pragma unroll
    for (int i = 0; i < 8; i++) { v[i] = s[tid + (i << 8)]; mx = fmaxf(mx, v[i]); }
#pragma unroll
    for (int o = 16; o; o >>= 1) mx = fmaxf(mx, __shfl_xor_sync(~0u, mx, o));
    __shared__ float red[8];
    if (lane == 0) red[warp] = mx;
    __syncthreads();
    mx = red[0];
#pragma unroll
    for (int w = 1; w < 8; w++) mx = fmaxf(mx, red[w]);

    float sum = 0.f;
#pragma unroll
    for (int i = 0; i < 8; i++) { v[i] = __expf(v[i] - mx); sum += v[i]; }
#pragma unroll
    for (int o = 16; o; o >>= 1) sum += __shfl_xor_sync(~0u, sum, o);
    __syncthreads();
    if (lane == 0) red[warp] = sum;
    __syncthreads();
    sum = 0.f;
#pragma unroll
    for (int w = 0; w < 8; w++) sum += red[w];
    float inv = 1.0f / sum;

    size_t base = row * (size_t)TT;
#pragma unroll
    for (int i = 0; i < 8; i++) {
        float p = v[i] * inv;
        bf16 h, l; split2(p, h, l);
        g_phi[base + tid + (i << 8)] = h;
        g_plo[base + tid + (i << 8)] = l;
    }
}

// ---------------- launch ----------------
extern "C" void kernel_launch(void* const* d_in, const int* in_sizes, int n_in,
                              void* d_out, int out_size) {
    (void)in_sizes; (void)n_in; (void)out_size;
    const float* x = (const float*)d_in[0];   // [4,2048,2048]
    const float* W = (const float*)d_in[1];   // [3072,2048]
    const float* b = (const float*)d_in[2];   // [3072]
    float* out = (float*)d_out;               // [4,2048,512]

    prep_x<<<16384, 256>>>(x);
    prep_w<<<9216, 256>>>(W, b);
    gemm3<0><<<dim3(9, 64, 1),  256>>>(nullptr);   // projection -> q_sum/K/V^T (split)
    gemm3<1><<<dim3(16, 16, 16), 256>>>(nullptr);  // scores -> S
    softmax_k<<<NBH * TT, 256>>>();                // S -> P (split)
    gemm3<2><<<dim3(1, 16, 16), 256>>>(out);       // P·V -> out
}

// round 3
// speedup vs baseline: 4.3473x; 1.3266x over previous
#include <cuda_runtime.h>
#include <cuda_bf16.h>
#include <math.h>

typedef __nv_bfloat16 bf16;

#define TT    2048
#define KDIM  2048
#define DH    128
#define NREDC 1152
#define MROWS 8192
#define NBH   16
#define SCALE 0.08838834764831845f   // 1/sqrt(128)

// ---------------- device scratch ----------------
__device__ bf16  g_xhi[(size_t)MROWS*KDIM];
__device__ bf16  g_xlo[(size_t)MROWS*KDIM];
__device__ bf16  g_whi[(size_t)NREDC*KDIM];
__device__ bf16  g_wlo[(size_t)NREDC*KDIM];
__device__ float g_bred[NREDC];
__device__ bf16  g_qhi[(size_t)MROWS*DH];
__device__ bf16  g_qlo[(size_t)MROWS*DH];
__device__ bf16  g_khi[(size_t)NBH*TT*DH];
__device__ bf16  g_klo[(size_t)NBH*TT*DH];
__device__ bf16  g_vhi[(size_t)NBH*TT*DH];    // V [bh][t][d]
__device__ bf16  g_vlo[(size_t)NBH*TT*DH];
__device__ bf16  g_vthi[(size_t)NBH*DH*TT];   // V^T [bh][d][t]
__device__ bf16  g_vtlo[(size_t)NBH*DH*TT];
__device__ float g_S  [(size_t)NBH*TT*TT];
__device__ bf16  g_phi[(size_t)NBH*TT*TT];
__device__ bf16  g_plo[(size_t)NBH*TT*TT];

// ---------------- helpers ----------------
__device__ __forceinline__ void split2(float v, bf16& h, bf16& l) {
    h = __float2bfloat16(v);
    l = __float2bfloat16(v - __bfloat162float(h));
}
__device__ __forceinline__ void cp16(void* sp, const void* gp) {
    unsigned s = (unsigned)__cvta_generic_to_shared(sp);
    asm volatile("cp.async.cg.shared.global [%0], [%1], 16;\n" :: "r"(s), "l"(gp));
}
// swizzled element offset inside a 128x32 bf16 tile (64B rows, 16B chunks)
#define SWZ(r, c) (((r) << 5) + ((((c) ^ (((r) >> 1) & 3))) << 3))

#define LDSM4(R, addr) \
    asm volatile("ldmatrix.sync.aligned.m8n8.x4.shared.b16 {%0,%1,%2,%3}, [%4];" \
        : "=r"((R)[0]), "=r"((R)[1]), "=r"((R)[2]), "=r"((R)[3]) : "r"(addr))

#define MMA16816(C, A, b0, b1) \
    asm volatile("mma.sync.aligned.m16n8k16.row.col.f32.bf16.bf16.f32 " \
        "{%0,%1,%2,%3},{%4,%5,%6,%7},{%8,%9},{%0,%1,%2,%3};" \
        : "+f"((C)[0]), "+f"((C)[1]), "+f"((C)[2]), "+f"((C)[3]) \
        : "r"((A)[0]), "r"((A)[1]), "r"((A)[2]), "r"((A)[3]), "r"(b0), "r"(b1))

// ---------------- prep ----------------
__global__ void prep_x(const float* __restrict__ x) {
    size_t i = ((size_t)blockIdx.x * 256 + threadIdx.x) * 4;
    float4 a = *(const float4*)(x + i);
    float arr[4] = {a.x, a.y, a.z, a.w};
#pragma unroll
    for (int j = 0; j < 4; j++) {
        bf16 h, l; split2(arr[j], h, l);
        g_xhi[i + j] = h;  g_xlo[i + j] = l;
    }
}

__global__ void prep_w(const float* __restrict__ W, const float* __restrict__ b) {
    int idx = blockIdx.x * 256 + threadIdx.x;
    int n = idx >> 11, c = idx & 2047;
    float v;
    if (n < 128) {
        v = 0.f;
#pragma unroll
        for (int h = 0; h < 16; h++) v += W[(size_t)(h * 128 + n) * KDIM + c];
        v *= SCALE;
    } else {
        v = W[(size_t)(n + 1920) * KDIM + c];
    }
    bf16 hh, ll; split2(v, hh, ll);
    g_whi[idx] = hh;  g_wlo[idx] = ll;

    if (idx < NREDC) {
        float bv;
        if (idx < 128) {
            bv = 0.f;
#pragma unroll
            for (int h = 0; h < 16; h++) bv += b[h * 128 + idx];
            bv *= SCALE;
        } else bv = b[idx + 1920];
        g_bred[idx] = bv;
    }
}

// ---------------- V transpose: [bh][t][d] -> [bh][d][t] ----------------
__global__ void transpose_v() {
    __shared__ bf16 th[32][33], tl[32][33];
    int t0 = blockIdx.x * 32, d0 = blockIdx.y * 32, bh = blockIdx.z;
    int tx = threadIdx.x, ty = threadIdx.y;
    const bf16* sh = g_vhi + (size_t)bh * TT * DH;
    const bf16* sl = g_vlo + (size_t)bh * TT * DH;
#pragma unroll
    for (int j = 0; j < 4; j++) {
        int t = t0 + ty + j * 8;
        th[ty + j * 8][tx] = sh[(size_t)t * DH + d0 + tx];
        tl[ty + j * 8][tx] = sl[(size_t)t * DH + d0 + tx];
    }
    __syncthreads();
    bf16* dh = g_vthi + (size_t)bh * DH * TT;
    bf16* dl = g_vtlo + (size_t)bh * DH * TT;
#pragma unroll
    for (int j = 0; j < 4; j++) {
        int d = d0 + ty + j * 8;
        dh[(size_t)d * TT + t0 + tx] = th[tx][ty + j * 8];
        dl[(size_t)d * TT + t0 + tx] = tl[tx][ty + j * 8];
    }
}

// ---------------- projection epilogue scatter (all coalesced) ----------------
__device__ __forceinline__ void proj_store(int m, int n, float v0, float v1) {
    bf16 h0, l0, h1, l1;
    split2(v0, h0, l0);  split2(v1, h1, l1);
    __nv_bfloat162 hv = __halves2bfloat162(h0, h1);
    __nv_bfloat162 lv = __halves2bfloat162(l0, l1);
    if (n < 128) {
        size_t i = (size_t)m * DH + n;
        *(__nv_bfloat162*)&g_qhi[i] = hv;  *(__nv_bfloat162*)&g_qlo[i] = lv;
    } else if (n < 640) {
        int i2 = n - 128;
        int bh = ((m >> 11) << 2) + (i2 >> 7);
        size_t i = (size_t)bh * TT * DH + (size_t)(m & 2047) * DH + (i2 & 127);
        *(__nv_bfloat162*)&g_khi[i] = hv;  *(__nv_bfloat162*)&g_klo[i] = lv;
    } else {
        int i2 = n - 640;
        int bh = ((m >> 11) << 2) + (i2 >> 7);
        size_t i = (size_t)bh * TT * DH + (size_t)(m & 2047) * DH + (i2 & 127);
        *(__nv_bfloat162*)&g_vhi[i] = hv;  *(__nv_bfloat162*)&g_vlo[i] = lv;
    }
}

// ---------------- fused 3-product split-bf16 GEMM ----------------
// One k-loop: per k-tile load Ahi/Alo/Bhi/Blo once, do hh + hl + lh mma.
// Block 128x128, k-tile 32, 8 warps (64x32 warp tiles), 2-stage cp.async.
// Dynamic smem: 2 stages x 4 tiles x 8KB = 64KB.
template<int MODE>
__global__ __launch_bounds__(256)
void gemm3(float* __restrict__ outp) {
    extern __shared__ bf16 sm[];

    const int tid  = threadIdx.x;
    const int lane = tid & 31;
    const int warp = tid >> 5;
    const int wm   = warp >> 2;
    const int wn   = warp & 3;
    const int m0   = blockIdx.y * 128;
    const int n0   = blockIdx.x * 128;
    const int z    = blockIdx.z;

    const bf16 *Ah, *Al, *Bh, *Bl;
    float* Cp = nullptr;
    int Kc, lda, ldb, ldc_;
    if (MODE == 0) {
        Ah = g_xhi; Al = g_xlo; Bh = g_whi; Bl = g_wlo;
        Kc = KDIM; lda = KDIM; ldb = KDIM; ldc_ = 0;
    } else if (MODE == 1) {
        size_t ao = (size_t)(z >> 2) * TT * DH, bo = (size_t)z * TT * DH;
        Ah = g_qhi + ao; Al = g_qlo + ao; Bh = g_khi + bo; Bl = g_klo + bo;
        Cp = g_S + (size_t)z * TT * TT;
        Kc = DH; lda = DH; ldb = DH; ldc_ = TT;
    } else {
        size_t ao = (size_t)z * TT * TT, bo = (size_t)z * DH * TT;
        Ah = g_phi + ao; Al = g_plo + ao; Bh = g_vthi + bo; Bl = g_vtlo + bo;
        Cp = outp + (size_t)(z >> 2) * TT * 512 + (size_t)(z & 3) * DH;
        Kc = TT; lda = TT; ldb = TT; ldc_ = 512;
    }
    const int KT = Kc / 32;

    float acc[4][4][4];
#pragma unroll
    for (int mi = 0; mi < 4; mi++)
#pragma unroll
        for (int ni = 0; ni < 4; ni++)
#pragma unroll
            for (int r = 0; r < 4; r++) acc[mi][ni][r] = 0.f;

    // stage layout (elements): [Ah 4096][Al 4096][Bh 4096][Bl 4096]
#define LOAD_STAGE(kt, buf) do {                                                \
    int k0_ = (kt) * 32;                                                        \
    bf16* st_ = sm + (buf) * 16384;                                             \
    _Pragma("unroll")                                                           \
    for (int p = 0; p < 2; p++) {                                               \
        int id = tid + (p << 8);                                                \
        int row = id >> 2, c = id & 3;                                          \
        int so = SWZ(row, c);                                                   \
        size_t ga = (size_t)(m0 + row) * lda + k0_ + (c << 3);                  \
        size_t gb = (size_t)(n0 + row) * ldb + k0_ + (c << 3);                  \
        cp16(st_ + so,         Ah + ga);                                        \
        cp16(st_ + 4096 + so,  Al + ga);                                        \
        cp16(st_ + 8192 + so,  Bh + gb);                                        \
        cp16(st_ + 12288 + so, Bl + gb);                                        \
    }                                                                           \
} while (0)

    LOAD_STAGE(0, 0);
    asm volatile("cp.async.commit_group;\n");

    for (int kt = 0; kt < KT; kt++) {
        if (kt + 1 < KT) {
            LOAD_STAGE(kt + 1, (kt + 1) & 1);
            asm volatile("cp.async.commit_group;\n");
            asm volatile("cp.async.wait_group 1;\n");
        } else {
            asm volatile("cp.async.wait_group 0;\n");
        }
        __syncthreads();

        const bf16* st = sm + (kt & 1) * 16384;
        unsigned base_ah = (unsigned)__cvta_generic_to_shared(st);
        unsigned base_al = base_ah + 4096 * 2;
        unsigned base_bh = base_ah + 8192 * 2;
        unsigned base_bl = base_ah + 12288 * 2;

#pragma unroll
        for (int ks = 0; ks < 32; ks += 16) {
            unsigned Af[4][4], Bhf[2][4], Blf[2][4];
            const int chk = (ks >> 3) + (lane >> 4);
#pragma unroll
            for (int mi = 0; mi < 4; mi++) {
                int r = wm * 64 + mi * 16 + (lane & 15);
                LDSM4(Af[mi], base_ah + SWZ(r, chk) * 2);
            }
#pragma unroll
            for (int bi = 0; bi < 2; bi++) {
                int r = wn * 32 + bi * 16 + (lane & 15);
                LDSM4(Bhf[bi], base_bh + SWZ(r, chk) * 2);
                LDSM4(Blf[bi], base_bl + SWZ(r, chk) * 2);
            }
            // hh + hl
#pragma unroll
            for (int mi = 0; mi < 4; mi++)
#pragma unroll
                for (int ni = 0; ni < 4; ni++) {
                    MMA16816(acc[mi][ni], Af[mi], Bhf[ni >> 1][ni & 1], Bhf[ni >> 1][(ni & 1) + 2]);
                    MMA16816(acc[mi][ni], Af[mi], Blf[ni >> 1][ni & 1], Blf[ni >> 1][(ni & 1) + 2]);
                }
            // lh (reuse Af slots)
#pragma unroll
            for (int mi = 0; mi < 4; mi++) {
                int r = wm * 64 + mi * 16 + (lane & 15);
                LDSM4(Af[mi], base_al + SWZ(r, chk) * 2);
            }
#pragma unroll
            for (int mi = 0; mi < 4; mi++)
#pragma unroll
                for (int ni = 0; ni < 4; ni++)
                    MMA16816(acc[mi][ni], Af[mi], Bhf[ni >> 1][ni & 1], Bhf[ni >> 1][(ni & 1) + 2]);
        }
        __syncthreads();
    }
#undef LOAD_STAGE

#pragma unroll
    for (int mi = 0; mi < 4; mi++)
#pragma unroll
        for (int ni = 0; ni < 4; ni++) {
            int mr = m0 + wm * 64 + mi * 16 + (lane >> 2);
            int nc = n0 + wn * 32 + ni * 8 + ((lane & 3) << 1);
            float* c = acc[mi][ni];
            if (MODE == 0) {
                float b0v = g_bred[nc], b1v = g_bred[nc + 1];
                proj_store(mr,     nc, c[0] + b0v, c[1] + b1v);
                proj_store(mr + 8, nc, c[2] + b0v, c[3] + b1v);
            } else {
                *(float2*)(Cp + (size_t)mr * ldc_ + nc)       = make_float2(c[0], c[1]);
                *(float2*)(Cp + (size_t)(mr + 8) * ldc_ + nc) = make_float2(c[2], c[3]);
            }
        }
}

// ---------------- softmax (S -> split P) ----------------
__global__ void softmax_k() {
    size_t row = blockIdx.x;
    const float* s = g_S + row * (size_t)TT;
    int tid = threadIdx.x, lane = tid & 31, warp = tid >> 5;

    float v[8];
    float mx = -1e30f;
#pragma unroll
    for (int i = 0; i < 8; i++) { v[i] = s[tid + (i << 8)]; mx = fmaxf(mx, v[i]); }
#pragma unroll
    for (int o = 16; o; o >>= 1) mx = fmaxf(mx, __shfl_xor_sync(~0u, mx, o));
    __shared__ float red[8];
    if (lane == 0) red[warp] = mx;
    __syncthreads();
    mx = red[0];
#pragma unroll
    for (int w = 1; w < 8; w++) mx = fmaxf(mx, red[w]);

    float sum = 0.f;
#pragma unroll
    for (int i = 0; i < 8; i++) { v[i] = __expf(v[i] - mx); sum += v[i]; }
#pragma unroll
    for (int o = 16; o; o >>= 1) sum += __shfl_xor_sync(~0u, sum, o);
    __syncthreads();
    if (lane == 0) red[warp] = sum;
    __syncthreads();
    sum = 0.f;
#pragma unroll
    for (int w = 0; w < 8; w++) sum += red[w];
    float inv = 1.0f / sum;

    size_t base = row * (size_t)TT;
#pragma unroll
    for (int i = 0; i < 8; i++) {
        float p = v[i] * inv;
        bf16 h, l; split2(p, h, l);
        g_phi[base + tid + (i << 8)] = h;
        g_plo[base + tid + (i << 8)] = l;
    }
}

// ---------------- launch ----------------
extern "C" void kernel_launch(void* const* d_in, const int* in_sizes, int n_in,
                              void* d_out, int out_size) {
    (void)in_sizes; (void)n_in; (void)out_size;
    const float* x = (const float*)d_in[0];
    const float* W = (const float*)d_in[1];
    const float* b = (const float*)d_in[2];
    float* out = (float*)d_out;

    const int SMEM = 2 * 16384 * (int)sizeof(bf16);   // 64KB
    cudaFuncSetAttribute(gemm3<0>, cudaFuncAttributeMaxDynamicSharedMemorySize, SMEM);
    cudaFuncSetAttribute(gemm3<1>, cudaFuncAttributeMaxDynamicSharedMemorySize, SMEM);
    cudaFuncSetAttribute(gemm3<2>, cudaFuncAttributeMaxDynamicSharedMemorySize, SMEM);

    prep_x<<<16384, 256>>>(x);
    prep_w<<<9216, 256>>>(W, b);
    gemm3<0><<<dim3(9, 64, 1), 256, SMEM>>>(nullptr);
    transpose_v<<<dim3(64, 4, 16), dim3(32, 8)>>>();
    gemm3<1><<<dim3(16, 16, 16), 256, SMEM>>>(nullptr);
    softmax_k<<<NBH * TT, 256>>>();
    gemm3<2><<<dim3(1, 16, 16), 256, SMEM>>>(out);
}

// round 5
// speedup vs baseline: 4.6824x; 1.0771x over previous
#include <cuda_runtime.h>
#include <cuda_bf16.h>
#include <cuda_fp16.h>
#include <cstdint>
#include <math.h>

typedef __nv_bfloat16 bf16;

#define TT    2048
#define KDIM  2048
#define DH    128
#define NREDC 1152
#define MROWS 8192
#define NBH   16
#define SCALE 0.08838834764831845f   // 1/sqrt(128)

// ---------------- device scratch ----------------
__device__ bf16   g_xhi[(size_t)MROWS*KDIM];
__device__ bf16   g_xlo[(size_t)MROWS*KDIM];
__device__ bf16   g_whi[(size_t)NREDC*KDIM];
__device__ bf16   g_wlo[(size_t)NREDC*KDIM];
__device__ float  g_bred[NREDC];
__device__ bf16   g_qhi[(size_t)MROWS*DH];
__device__ bf16   g_qlo[(size_t)MROWS*DH];
__device__ bf16   g_khi[(size_t)NBH*TT*DH];
__device__ bf16   g_klo[(size_t)NBH*TT*DH];
__device__ bf16   g_vhi[(size_t)NBH*TT*DH];    // V [bh][t][d] (bf16 split)
__device__ bf16   g_vlo[(size_t)NBH*TT*DH];
__device__ __half g_vth[(size_t)NBH*DH*TT];    // V^T [bh][d][t] (fp16 split)
__device__ __half g_vtl[(size_t)NBH*DH*TT];
__device__ float  g_S  [(size_t)NBH*TT*TT];
__device__ __half g_p16[(size_t)NBH*TT*TT];    // P fp16 (single)

// ---------------- helpers ----------------
__device__ __forceinline__ void split2(float v, bf16& h, bf16& l) {
    h = __float2bfloat16(v);
    l = __float2bfloat16(v - __bfloat162float(h));
}
__device__ __forceinline__ void split2h(float v, __half& h, __half& l) {
    h = __float2half(v);
    l = __float2half(v - __half2float(h));
}
__device__ __forceinline__ void cp16(void* sp, const void* gp) {
    unsigned s = (unsigned)__cvta_generic_to_shared(sp);
    asm volatile("cp.async.cg.shared.global [%0], [%1], 16;\n" :: "r"(s), "l"(gp));
}
#define CP_COMMIT() asm volatile("cp.async.commit_group;\n")
#define CP_WAIT(n)  asm volatile("cp.async.wait_group %0;\n" :: "n"(n))

// swizzled element offset inside a 128x32 16-bit tile (64B rows, 16B chunks)
#define SWZ(r, c) (((r) << 5) + ((((c) ^ (((r) >> 1) & 3))) << 3))

#define LDSM4(R, addr) \
    asm volatile("ldmatrix.sync.aligned.m8n8.x4.shared.b16 {%0,%1,%2,%3}, [%4];" \
        : "=r"((R)[0]), "=r"((R)[1]), "=r"((R)[2]), "=r"((R)[3]) : "r"(addr))

#define MMA_BF16(C, A, b0, b1) \
    asm volatile("mma.sync.aligned.m16n8k16.row.col.f32.bf16.bf16.f32 " \
        "{%0,%1,%2,%3},{%4,%5,%6,%7},{%8,%9},{%0,%1,%2,%3};" \
        : "+f"((C)[0]), "+f"((C)[1]), "+f"((C)[2]), "+f"((C)[3]) \
        : "r"((A)[0]), "r"((A)[1]), "r"((A)[2]), "r"((A)[3]), "r"(b0), "r"(b1))

#define MMA_F16(C, A, b0, b1) \
    asm volatile("mma.sync.aligned.m16n8k16.row.col.f32.f16.f16.f32 " \
        "{%0,%1,%2,%3},{%4,%5,%6,%7},{%8,%9},{%0,%1,%2,%3};" \
        : "+f"((C)[0]), "+f"((C)[1]), "+f"((C)[2]), "+f"((C)[3]) \
        : "r"((A)[0]), "r"((A)[1]), "r"((A)[2]), "r"((A)[3]), "r"(b0), "r"(b1))

// ---------------- prep ----------------
__global__ void prep_x(const float* __restrict__ x) {
    size_t i = ((size_t)blockIdx.x * 256 + threadIdx.x) * 4;
    float4 a = *(const float4*)(x + i);
    float arr[4] = {a.x, a.y, a.z, a.w};
#pragma unroll
    for (int j = 0; j < 4; j++) {
        bf16 h, l; split2(arr[j], h, l);
        g_xhi[i + j] = h;  g_xlo[i + j] = l;
    }
}

__global__ void prep_w(const float* __restrict__ W, const float* __restrict__ b) {
    int idx = blockIdx.x * 256 + threadIdx.x;
    int n = idx >> 11, c = idx & 2047;
    float v;
    if (n < 128) {
        v = 0.f;
#pragma unroll
        for (int h = 0; h < 16; h++) v += W[(size_t)(h * 128 + n) * KDIM + c];
        v *= SCALE;
    } else {
        v = W[(size_t)(n + 1920) * KDIM + c];
    }
    bf16 hh, ll; split2(v, hh, ll);
    g_whi[idx] = hh;  g_wlo[idx] = ll;

    if (idx < NREDC) {
        float bv;
        if (idx < 128) {
            bv = 0.f;
#pragma unroll
            for (int h = 0; h < 16; h++) bv += b[h * 128 + idx];
            bv *= SCALE;
        } else bv = b[idx + 1920];
        g_bred[idx] = bv;
    }
}

// ---------------- V transpose + bf16-split -> fp16-split ----------------
__global__ void transpose_v() {
    __shared__ __half th[32][33], tl[32][33];
    int t0 = blockIdx.x * 32, d0 = blockIdx.y * 32, bh = blockIdx.z;
    int tx = threadIdx.x, ty = threadIdx.y;
    const bf16* sh = g_vhi + (size_t)bh * TT * DH;
    const bf16* sl = g_vlo + (size_t)bh * TT * DH;
#pragma unroll
    for (int j = 0; j < 4; j++) {
        int t = t0 + ty + j * 8;
        size_t i = (size_t)t * DH + d0 + tx;
        float v = __bfloat162float(sh[i]) + __bfloat162float(sl[i]);
        __half h, l; split2h(v, h, l);
        th[ty + j * 8][tx] = h;
        tl[ty + j * 8][tx] = l;
    }
    __syncthreads();
    __half* dh = g_vth + (size_t)bh * DH * TT;
    __half* dl = g_vtl + (size_t)bh * DH * TT;
#pragma unroll
    for (int j = 0; j < 4; j++) {
        int d = d0 + ty + j * 8;
        dh[(size_t)d * TT + t0 + tx] = th[tx][ty + j * 8];
        dl[(size_t)d * TT + t0 + tx] = tl[tx][ty + j * 8];
    }
}

// ---------------- projection epilogue scatter ----------------
__device__ __forceinline__ void proj_store(int m, int n, float v0, float v1) {
    bf16 h0, l0, h1, l1;
    split2(v0, h0, l0);  split2(v1, h1, l1);
    __nv_bfloat162 hv = __halves2bfloat162(h0, h1);
    __nv_bfloat162 lv = __halves2bfloat162(l0, l1);
    if (n < 128) {
        size_t i = (size_t)m * DH + n;
        *(__nv_bfloat162*)&g_qhi[i] = hv;  *(__nv_bfloat162*)&g_qlo[i] = lv;
    } else if (n < 640) {
        int i2 = n - 128;
        int bh = ((m >> 11) << 2) + (i2 >> 7);
        size_t i = (size_t)bh * TT * DH + (size_t)(m & 2047) * DH + (i2 & 127);
        *(__nv_bfloat162*)&g_khi[i] = hv;  *(__nv_bfloat162*)&g_klo[i] = lv;
    } else {
        int i2 = n - 640;
        int bh = ((m >> 11) << 2) + (i2 >> 7);
        size_t i = (size_t)bh * TT * DH + (size_t)(m & 2047) * DH + (i2 & 127);
        *(__nv_bfloat162*)&g_vhi[i] = hv;  *(__nv_bfloat162*)&g_vlo[i] = lv;
    }
}

// ---------------- mma.sync GEMM, 3-stage pipeline, 1 sync/iter ----------------
// MODE 0: proj  (bf16, 3 products hh,hl,lh)    A=x split, B=w split
// MODE 1: score (bf16, 3 products)             A=q split, B=k split
// MODE 2: PV    (fp16, 2 products A*Bh, A*Bl)  A=P single, B=V^T split
template<int MODE>
__global__ __launch_bounds__(256, 2)
void gemm3(float* __restrict__ outp) {
    extern __shared__ uint16_t sm[];
    constexpr int NTILE = (MODE == 2) ? 3 : 4;
    constexpr int STAGE = NTILE * 4096;   // 16-bit elements per stage

    const int tid  = threadIdx.x;
    const int lane = tid & 31;
    const int warp = tid >> 5;
    const int wm   = warp >> 2;
    const int wn   = warp & 3;
    const int m0   = blockIdx.y * 128;
    const int n0   = blockIdx.x * 128;
    const int z    = blockIdx.z;

    const uint16_t *Ah, *Al = nullptr, *Bh, *Bl;
    float* Cp = nullptr;
    int Kc, lda, ldb, ldc_;
    if (MODE == 0) {
        Ah = (const uint16_t*)g_xhi; Al = (const uint16_t*)g_xlo;
        Bh = (const uint16_t*)g_whi; Bl = (const uint16_t*)g_wlo;
        Kc = KDIM; lda = KDIM; ldb = KDIM; ldc_ = 0;
    } else if (MODE == 1) {
        size_t ao = (size_t)(z >> 2) * TT * DH, bo = (size_t)z * TT * DH;
        Ah = (const uint16_t*)(g_qhi + ao); Al = (const uint16_t*)(g_qlo + ao);
        Bh = (const uint16_t*)(g_khi + bo); Bl = (const uint16_t*)(g_klo + bo);
        Cp = g_S + (size_t)z * TT * TT;
        Kc = DH; lda = DH; ldb = DH; ldc_ = TT;
    } else {
        size_t ao = (size_t)z * TT * TT, bo = (size_t)z * DH * TT;
        Ah = (const uint16_t*)(g_p16 + ao);
        Bh = (const uint16_t*)(g_vth + bo); Bl = (const uint16_t*)(g_vtl + bo);
        Cp = outp + (size_t)(z >> 2) * TT * 512 + (size_t)(z & 3) * DH;
        Kc = TT; lda = TT; ldb = TT; ldc_ = 512;
    }
    const int KT = Kc / 32;

    float acc[4][4][4];
#pragma unroll
    for (int mi = 0; mi < 4; mi++)
#pragma unroll
        for (int ni = 0; ni < 4; ni++)
#pragma unroll
            for (int r = 0; r < 4; r++) acc[mi][ni][r] = 0.f;

#define LOAD_STAGE(kt, buf) do {                                                \
    int k0_ = (kt) * 32;                                                        \
    uint16_t* st_ = sm + (buf) * STAGE;                                         \
    _Pragma("unroll")                                                           \
    for (int p = 0; p < 2; p++) {                                               \
        int id = tid + (p << 8);                                                \
        int row = id >> 2, c = id & 3;                                          \
        int so = SWZ(row, c);                                                   \
        size_t ga = (size_t)(m0 + row) * lda + k0_ + (c << 3);                  \
        size_t gb = (size_t)(n0 + row) * ldb + k0_ + (c << 3);                  \
        if (MODE == 2) {                                                        \
            cp16(st_ + so,        Ah + ga);                                     \
            cp16(st_ + 4096 + so, Bh + gb);                                     \
            cp16(st_ + 8192 + so, Bl + gb);                                     \
        } else {                                                                \
            cp16(st_ + so,         Ah + ga);                                    \
            cp16(st_ + 4096 + so,  Al + ga);                                    \
            cp16(st_ + 8192 + so,  Bh + gb);                                    \
            cp16(st_ + 12288 + so, Bl + gb);                                    \
        }                                                                       \
    }                                                                           \
} while (0)

    LOAD_STAGE(0, 0); CP_COMMIT();
    LOAD_STAGE(1, 1); CP_COMMIT();

    int buf = 0;
    for (int kt = 0; kt < KT; kt++) {
        CP_WAIT(1);
        __syncthreads();
        if (kt + 2 < KT) {
            int nb = buf + 2; if (nb >= 3) nb -= 3;
            LOAD_STAGE(kt + 2, nb);
            CP_COMMIT();
        }

        const uint16_t* st = sm + buf * STAGE;
        unsigned base_a  = (unsigned)__cvta_generic_to_shared(st);
        unsigned base_al = base_a + 4096 * 2;
        unsigned base_bh = base_a + (MODE == 2 ? 4096 : 8192) * 2;
        unsigned base_bl = base_a + (MODE == 2 ? 8192 : 12288) * 2;

#pragma unroll
        for (int ks = 0; ks < 32; ks += 16) {
            unsigned Af[4][4], Bhf[2][4], Blf[2][4];
            const int chk = (ks >> 3) + (lane >> 4);
#pragma unroll
            for (int mi = 0; mi < 4; mi++) {
                int r = wm * 64 + mi * 16 + (lane & 15);
                LDSM4(Af[mi], base_a + SWZ(r, chk) * 2);
            }
#pragma unroll
            for (int bi = 0; bi < 2; bi++) {
                int r = wn * 32 + bi * 16 + (lane & 15);
                LDSM4(Bhf[bi], base_bh + SWZ(r, chk) * 2);
                LDSM4(Blf[bi], base_bl + SWZ(r, chk) * 2);
            }
            if (MODE == 2) {
#pragma unroll
                for (int mi = 0; mi < 4; mi++)
#pragma unroll
                    for (int ni = 0; ni < 4; ni++) {
                        MMA_F16(acc[mi][ni], Af[mi], Bhf[ni >> 1][ni & 1], Bhf[ni >> 1][(ni & 1) + 2]);
                        MMA_F16(acc[mi][ni], Af[mi], Blf[ni >> 1][ni & 1], Blf[ni >> 1][(ni & 1) + 2]);
                    }
            } else {
#pragma unroll
                for (int mi = 0; mi < 4; mi++)
#pragma unroll
                    for (int ni = 0; ni < 4; ni++) {
                        MMA_BF16(acc[mi][ni], Af[mi], Bhf[ni >> 1][ni & 1], Bhf[ni >> 1][(ni & 1) + 2]);
                        MMA_BF16(acc[mi][ni], Af[mi], Blf[ni >> 1][ni & 1], Blf[ni >> 1][(ni & 1) + 2]);
                    }
#pragma unroll
                for (int mi = 0; mi < 4; mi++) {
                    int r = wm * 64 + mi * 16 + (lane & 15);
                    LDSM4(Af[mi], base_al + SWZ(r, chk) * 2);
                }
#pragma unroll
                for (int mi = 0; mi < 4; mi++)
#pragma unroll
                    for (int ni = 0; ni < 4; ni++)
                        MMA_BF16(acc[mi][ni], Af[mi], Bhf[ni >> 1][ni & 1], Bhf[ni >> 1][(ni & 1) + 2]);
            }
        }
        __syncthreads();
        buf++; if (buf >= 3) buf = 0;
    }
#undef LOAD_STAGE

#pragma unroll
    for (int mi = 0; mi < 4; mi++)
#pragma unroll
        for (int ni = 0; ni < 4; ni++) {
            int mr = m0 + wm * 64 + mi * 16 + (lane >> 2);
            int nc = n0 + wn * 32 + ni * 8 + ((lane & 3) << 1);
            float* c = acc[mi][ni];
            if (MODE == 0) {
                float b0v = g_bred[nc], b1v = g_bred[nc + 1];
                proj_store(mr,     nc, c[0] + b0v, c[1] + b1v);
                proj_store(mr + 8, nc, c[2] + b0v, c[3] + b1v);
            } else {
                *(float2*)(Cp + (size_t)mr * ldc_ + nc)       = make_float2(c[0], c[1]);
                *(float2*)(Cp + (size_t)(mr + 8) * ldc_ + nc) = make_float2(c[2], c[3]);
            }
        }
}

// ---------------- softmax (S fp32 -> P fp16) ----------------
__global__ void softmax_k() {
    size_t row = blockIdx.x;
    const float4* s = (const float4*)(g_S + row * (size_t)TT);
    int tid = threadIdx.x, lane = tid & 31, warp = tid >> 5;

    float4 a = s[tid];          // cols 4t .. 4t+3
    float4 b = s[tid + 256];    // cols 1024+4t ..
    float v[8] = {a.x, a.y, a.z, a.w, b.x, b.y, b.z, b.w};

    float mx = -1e30f;
#pragma unroll
    for (int i = 0; i < 8; i++) mx = fmaxf(mx, v[i]);
#pragma unroll
    for (int o = 16; o; o >>= 1) mx = fmaxf(mx, __shfl_xor_sync(~0u, mx, o));
    __shared__ float red[8];
    if (lane == 0) red[warp] = mx;
    __syncthreads();
    mx = red[0];
#pragma unroll
    for (int w = 1; w < 8; w++) mx = fmaxf(mx, red[w]);

    float sum = 0.f;
#pragma unroll
    for (int i = 0; i < 8; i++) { v[i] = __expf(v[i] - mx); sum += v[i]; }
#pragma unroll
    for (int o = 16; o; o >>= 1) sum += __shfl_xor_sync(~0u, sum, o);
    __syncthreads();
    if (lane == 0) red[warp] = sum;
    __syncthreads();
    sum = 0.f;
#pragma unroll
    for (int w = 0; w < 8; w++) sum += red[w];
    float inv = 1.0f / sum;

    __half* p = g_p16 + row * (size_t)TT;
    *(__half2*)(p + tid * 4)            = __floats2half2_rn(v[0] * inv, v[1] * inv);
    *(__half2*)(p + tid * 4 + 2)        = __floats2half2_rn(v[2] * inv, v[3] * inv);
    *(__half2*)(p + 1024 + tid * 4)     = __floats2half2_rn(v[4] * inv, v[5] * inv);
    *(__half2*)(p + 1024 + tid * 4 + 2) = __floats2half2_rn(v[6] * inv, v[7] * inv);
}

// ---------------- launch ----------------
extern "C" void kernel_launch(void* const* d_in, const int* in_sizes, int n_in,
                              void* d_out, int out_size) {
    (void)in_sizes; (void)n_in; (void)out_size;
    const float* x = (const float*)d_in[0];
    const float* W = (const float*)d_in[1];
    const float* b = (const float*)d_in[2];
    float* out = (float*)d_out;

    const int SMEM_AB = 3 * 4 * 4096 * 2;   // 96KB (MODE 0/1)
    const int SMEM_PV = 3 * 3 * 4096 * 2;   // 72KB (MODE 2)
    cudaFuncSetAttribute(gemm3<0>, cudaFuncAttributeMaxDynamicSharedMemorySize, SMEM_AB);
    cudaFuncSetAttribute(gemm3<1>, cudaFuncAttributeMaxDynamicSharedMemorySize, SMEM_AB);
    cudaFuncSetAttribute(gemm3<2>, cudaFuncAttributeMaxDynamicSharedMemorySize, SMEM_PV);

    prep_x<<<16384, 256>>>(x);
    prep_w<<<9216, 256>>>(W, b);
    gemm3<0><<<dim3(9, 64, 1), 256, SMEM_AB>>>(nullptr);
    transpose_v<<<dim3(64, 4, 16), dim3(32, 8)>>>();
    gemm3<1><<<dim3(16, 16, 16), 256, SMEM_AB>>>(nullptr);
    softmax_k<<<NBH * TT, 256>>>();
    gemm3<2><<<dim3(1, 16, 16), 256, SMEM_PV>>>(out);
}

// round 7
// speedup vs baseline: 5.1537x; 1.1006x over previous
#include <cuda_runtime.h>
#include <cuda_bf16.h>
#include <cuda_fp16.h>
#include <cstdint>
#include <math.h>

typedef __nv_bfloat16 bf16;

#define TT    2048
#define KDIM  2048
#define DH    128
#define NREDC 1152
#define MROWS 8192
#define NBH   16
#define SCALE 0.08838834764831845f   // 1/sqrt(128)

// ---------------- device scratch ----------------
__device__ bf16   g_xhi[(size_t)MROWS*KDIM];
__device__ bf16   g_xlo[(size_t)MROWS*KDIM];
__device__ bf16   g_whi[(size_t)NREDC*KDIM];
__device__ bf16   g_wlo[(size_t)NREDC*KDIM];
__device__ float  g_bred[NREDC];
__device__ bf16   g_qhi[(size_t)MROWS*DH];
__device__ bf16   g_qlo[(size_t)MROWS*DH];
__device__ bf16   g_khi[(size_t)NBH*TT*DH];
__device__ bf16   g_klo[(size_t)NBH*TT*DH];
__device__ bf16   g_vhi[(size_t)NBH*TT*DH];    // V [bh][t][d] (bf16 split)
__device__ bf16   g_vlo[(size_t)NBH*TT*DH];
__device__ __half g_vth[(size_t)NBH*DH*TT];    // V^T [bh][d][t] (fp16 split)
__device__ __half g_vtl[(size_t)NBH*DH*TT];

// ---------------- helpers ----------------
__device__ __forceinline__ void split2(float v, bf16& h, bf16& l) {
    h = __float2bfloat16(v);
    l = __float2bfloat16(v - __bfloat162float(h));
}
__device__ __forceinline__ void split2h(float v, __half& h, __half& l) {
    h = __float2half(v);
    l = __float2half(v - __half2float(h));
}
__device__ __forceinline__ unsigned h2u(__half2 h) {
    return *reinterpret_cast<unsigned*>(&h);
}
__device__ __forceinline__ void cp16(void* sp, const void* gp) {
    unsigned s = (unsigned)__cvta_generic_to_shared(sp);
    asm volatile("cp.async.cg.shared.global [%0], [%1], 16;\n" :: "r"(s), "l"(gp));
}
__device__ __forceinline__ void cp16s(unsigned s, const void* gp) {
    asm volatile("cp.async.cg.shared.global [%0], [%1], 16;\n" :: "r"(s), "l"(gp));
}
#define CP_COMMIT() asm volatile("cp.async.commit_group;\n")
#define CP_WAIT(n)  asm volatile("cp.async.wait_group %0;\n" :: "n"(n))

// swizzled element offset inside an Nx32 16-bit tile (64B rows, 16B chunks)
#define SWZ(r, c) (((r) << 5) + ((((c) ^ (((r) >> 1) & 3))) << 3))

#define LDSM4(R, addr) \
    asm volatile("ldmatrix.sync.aligned.m8n8.x4.shared.b16 {%0,%1,%2,%3}, [%4];" \
        : "=r"((R)[0]), "=r"((R)[1]), "=r"((R)[2]), "=r"((R)[3]) : "r"(addr))

#define MMA_BF16(C, A, b0, b1) \
    asm volatile("mma.sync.aligned.m16n8k16.row.col.f32.bf16.bf16.f32 " \
        "{%0,%1,%2,%3},{%4,%5,%6,%7},{%8,%9},{%0,%1,%2,%3};" \
        : "+f"((C)[0]), "+f"((C)[1]), "+f"((C)[2]), "+f"((C)[3]) \
        : "r"((A)[0]), "r"((A)[1]), "r"((A)[2]), "r"((A)[3]), "r"(b0), "r"(b1))

#define MMA_F16(C, A, b0, b1) \
    asm volatile("mma.sync.aligned.m16n8k16.row.col.f32.f16.f16.f32 " \
        "{%0,%1,%2,%3},{%4,%5,%6,%7},{%8,%9},{%0,%1,%2,%3};" \
        : "+f"((C)[0]), "+f"((C)[1]), "+f"((C)[2]), "+f"((C)[3]) \
        : "r"((A)[0]), "r"((A)[1]), "r"((A)[2]), "r"((A)[3]), "r"(b0), "r"(b1))

// ---------------- prep ----------------
__global__ void prep_x(const float* __restrict__ x) {
    size_t i = ((size_t)blockIdx.x * 256 + threadIdx.x) * 4;
    float4 a = *(const float4*)(x + i);
    float arr[4] = {a.x, a.y, a.z, a.w};
#pragma unroll
    for (int j = 0; j < 4; j++) {
        bf16 h, l; split2(arr[j], h, l);
        g_xhi[i + j] = h;  g_xlo[i + j] = l;
    }
}

__global__ void prep_w(const float* __restrict__ W, const float* __restrict__ b) {
    int idx = blockIdx.x * 256 + threadIdx.x;
    int n = idx >> 11, c = idx & 2047;
    float v;
    if (n < 128) {
        v = 0.f;
#pragma unroll
        for (int h = 0; h < 16; h++) v += W[(size_t)(h * 128 + n) * KDIM + c];
        v *= SCALE;
    } else {
        v = W[(size_t)(n + 1920) * KDIM + c];
    }
    bf16 hh, ll; split2(v, hh, ll);
    g_whi[idx] = hh;  g_wlo[idx] = ll;

    if (idx < NREDC) {
        float bv;
        if (idx < 128) {
            bv = 0.f;
#pragma unroll
            for (int h = 0; h < 16; h++) bv += b[h * 128 + idx];
            bv *= SCALE;
        } else bv = b[idx + 1920];
        g_bred[idx] = bv;
    }
}

// ---------------- V transpose + bf16-split -> fp16-split ----------------
__global__ void transpose_v() {
    __shared__ __half th[32][33], tl[32][33];
    int t0 = blockIdx.x * 32, d0 = blockIdx.y * 32, bh = blockIdx.z;
    int tx = threadIdx.x, ty = threadIdx.y;
    const bf16* sh = g_vhi + (size_t)bh * TT * DH;
    const bf16* sl = g_vlo + (size_t)bh * TT * DH;
#pragma unroll
    for (int j = 0; j < 4; j++) {
        int t = t0 + ty + j * 8;
        size_t i = (size_t)t * DH + d0 + tx;
        float v = __bfloat162float(sh[i]) + __bfloat162float(sl[i]);
        __half h, l; split2h(v, h, l);
        th[ty + j * 8][tx] = h;
        tl[ty + j * 8][tx] = l;
    }
    __syncthreads();
    __half* dh = g_vth + (size_t)bh * DH * TT;
    __half* dl = g_vtl + (size_t)bh * DH * TT;
#pragma unroll
    for (int j = 0; j < 4; j++) {
        int d = d0 + ty + j * 8;
        dh[(size_t)d * TT + t0 + tx] = th[tx][ty + j * 8];
        dl[(size_t)d * TT + t0 + tx] = tl[tx][ty + j * 8];
    }
}

// ---------------- projection epilogue scatter ----------------
__device__ __forceinline__ void proj_store(int m, int n, float v0, float v1) {
    bf16 h0, l0, h1, l1;
    split2(v0, h0, l0);  split2(v1, h1, l1);
    __nv_bfloat162 hv = __halves2bfloat162(h0, h1);
    __nv_bfloat162 lv = __halves2bfloat162(l0, l1);
    if (n < 128) {
        size_t i = (size_t)m * DH + n;
        *(__nv_bfloat162*)&g_qhi[i] = hv;  *(__nv_bfloat162*)&g_qlo[i] = lv;
    } else if (n < 640) {
        int i2 = n - 128;
        int bh = ((m >> 11) << 2) + (i2 >> 7);
        size_t i = (size_t)bh * TT * DH + (size_t)(m & 2047) * DH + (i2 & 127);
        *(__nv_bfloat162*)&g_khi[i] = hv;  *(__nv_bfloat162*)&g_klo[i] = lv;
    } else {
        int i2 = n - 640;
        int bh = ((m >> 11) << 2) + (i2 >> 7);
        size_t i = (size_t)bh * TT * DH + (size_t)(m & 2047) * DH + (i2 & 127);
        *(__nv_bfloat162*)&g_vhi[i] = hv;  *(__nv_bfloat162*)&g_vlo[i] = lv;
    }
}

// ---------------- projection GEMM (bf16 3-product, 3-stage pipeline) ----------------
__global__ __launch_bounds__(256, 2)
void gemm_proj(int dummy) {
    extern __shared__ uint16_t sm[];
    constexpr int STAGE = 4 * 4096;

    const int tid  = threadIdx.x;
    const int lane = tid & 31;
    const int warp = tid >> 5;
    const int wm   = warp >> 2;
    const int wn   = warp & 3;
    const int m0   = blockIdx.y * 128;
    const int n0   = blockIdx.x * 128;

    const uint16_t* Ah = (const uint16_t*)g_xhi;
    const uint16_t* Al = (const uint16_t*)g_xlo;
    const uint16_t* Bh = (const uint16_t*)g_whi;
    const uint16_t* Bl = (const uint16_t*)g_wlo;
    const int KT = KDIM / 32;

    float acc[4][4][4];
#pragma unroll
    for (int mi = 0; mi < 4; mi++)
#pragma unroll
        for (int ni = 0; ni < 4; ni++)
#pragma unroll
            for (int r = 0; r < 4; r++) acc[mi][ni][r] = 0.f;

#define LOAD_STAGE(kt, buf) do {                                                \
    int k0_ = (kt) * 32;                                                        \
    uint16_t* st_ = sm + (buf) * STAGE;                                         \
    _Pragma("unroll")                                                           \
    for (int p = 0; p < 2; p++) {                                               \
        int id = tid + (p << 8);                                                \
        int row = id >> 2, c = id & 3;                                          \
        int so = SWZ(row, c);                                                   \
        size_t ga = (size_t)(m0 + row) * KDIM + k0_ + (c << 3);                 \
        size_t gb = (size_t)(n0 + row) * KDIM + k0_ + (c << 3);                 \
        cp16(st_ + so,         Ah + ga);                                        \
        cp16(st_ + 4096 + so,  Al + ga);                                        \
        cp16(st_ + 8192 + so,  Bh + gb);                                        \
        cp16(st_ + 12288 + so, Bl + gb);                                        \
    }                                                                           \
} while (0)

    LOAD_STAGE(0, 0); CP_COMMIT();
    LOAD_STAGE(1, 1); CP_COMMIT();

    int buf = 0;
    for (int kt = 0; kt < KT; kt++) {
        CP_WAIT(1);
        __syncthreads();
        if (kt + 2 < KT) {
            int nb = buf + 2; if (nb >= 3) nb -= 3;
            LOAD_STAGE(kt + 2, nb);
            CP_COMMIT();
        }

        const uint16_t* st = sm + buf * STAGE;
        unsigned base_a  = (unsigned)__cvta_generic_to_shared(st);
        unsigned base_al = base_a + 4096 * 2;
        unsigned base_bh = base_a + 8192 * 2;
        unsigned base_bl = base_a + 12288 * 2;

#pragma unroll
        for (int ks = 0; ks < 32; ks += 16) {
            unsigned Af[4][4], Bhf[2][4], Blf[2][4];
            const int chk = (ks >> 3) + (lane >> 4);
#pragma unroll
            for (int mi = 0; mi < 4; mi++) {
                int r = wm * 64 + mi * 16 + (lane & 15);
                LDSM4(Af[mi], base_a + SWZ(r, chk) * 2);
            }
#pragma unroll
            for (int bi = 0; bi < 2; bi++) {
                int r = wn * 32 + bi * 16 + (lane & 15);
                LDSM4(Bhf[bi], base_bh + SWZ(r, chk) * 2);
                LDSM4(Blf[bi], base_bl + SWZ(r, chk) * 2);
            }
#pragma unroll
            for (int mi = 0; mi < 4; mi++)
#pragma unroll
                for (int ni = 0; ni < 4; ni++) {
                    MMA_BF16(acc[mi][ni], Af[mi], Bhf[ni >> 1][ni & 1], Bhf[ni >> 1][(ni & 1) + 2]);
                    MMA_BF16(acc[mi][ni], Af[mi], Blf[ni >> 1][ni & 1], Blf[ni >> 1][(ni & 1) + 2]);
                }
#pragma unroll
            for (int mi = 0; mi < 4; mi++) {
                int r = wm * 64 + mi * 16 + (lane & 15);
                LDSM4(Af[mi], base_al + SWZ(r, chk) * 2);
            }
#pragma unroll
            for (int mi = 0; mi < 4; mi++)
#pragma unroll
                for (int ni = 0; ni < 4; ni++)
                    MMA_BF16(acc[mi][ni], Af[mi], Bhf[ni >> 1][ni & 1], Bhf[ni >> 1][(ni & 1) + 2]);
        }
        __syncthreads();
        buf++; if (buf >= 3) buf = 0;
    }
#undef LOAD_STAGE

#pragma unroll
    for (int mi = 0; mi < 4; mi++)
#pragma unroll
        for (int ni = 0; ni < 4; ni++) {
            int mr = m0 + wm * 64 + mi * 16 + (lane >> 2);
            int nc = n0 + wn * 32 + ni * 8 + ((lane & 3) << 1);
            float* c = acc[mi][ni];
            float b0v = g_bred[nc], b1v = g_bred[nc + 1];
            proj_store(mr,     nc, c[0] + b0v, c[1] + b1v);
            proj_store(mr + 8, nc, c[2] + b0v, c[3] + b1v);
        }
}

// ---------------- fused flash attention ----------------
// CTA: 128 q rows x one bh. 8 warps; warp w owns q rows w*16..w*16+15.
// KV tiles of 64 keys, double-buffered. Q resident in smem.
// smem (16-bit elems): Qhi[0,16384) Qlo[16384,32768)
//   stage s at 32768+s*32768: Khi[0,8192) Klo[8192,16384) Vthi[16384,24576) Vtlo[24576,32768)
#define FL_ELEMS (32768 + 2 * 32768)
#define FL_SMEM  (FL_ELEMS * 2)

__global__ __launch_bounds__(256)
void flash_attn(float* __restrict__ out) {
    extern __shared__ uint16_t fs[];
    const unsigned sb = (unsigned)__cvta_generic_to_shared(fs);

    const int tid  = threadIdx.x;
    const int lane = tid & 31;
    const int warp = tid >> 5;
    const int bh   = blockIdx.y;
    const int b    = bh >> 2;
    const int kvh  = bh & 3;
    const int q0   = blockIdx.x * 128;

    // ---- load Q (hi+lo), 16 chunks/thread ----
    {
        const uint16_t* qsrc0 = (const uint16_t*)g_qhi;
        const uint16_t* qsrc1 = (const uint16_t*)g_qlo;
#pragma unroll
        for (int p = 0; p < 16; p++) {
            int id = tid + (p << 8);
            int part = id >> 11, cid = id & 2047;
            int row = cid >> 4, c8 = cid & 15;
            unsigned dst = (unsigned)(part * 16384 + (c8 >> 2) * 4096 + SWZ(row, c8 & 3));
            const uint16_t* src = (part ? qsrc1 : qsrc0) + (size_t)(b * TT + q0 + row) * DH + c8 * 8;
            cp16s(sb + dst * 2, src);
        }
    }
    CP_COMMIT();

#define LOADKV(kt_, buf_) do {                                                   \
    const uint16_t* ksrc0 = (const uint16_t*)g_khi;                              \
    const uint16_t* ksrc1 = (const uint16_t*)g_klo;                              \
    const uint16_t* vsrc0 = (const uint16_t*)g_vth;                              \
    const uint16_t* vsrc1 = (const uint16_t*)g_vtl;                              \
    unsigned stg = 32768u + (buf_) * 32768u;                                     \
    _Pragma("unroll")                                                            \
    for (int p = 0; p < 16; p++) {                                               \
        int id = tid + (p << 8);                                                 \
        int part = id >> 10, cid = id & 1023;                                    \
        if (part < 2) {                                                          \
            int row = cid >> 4, c8 = cid & 15;                                   \
            unsigned dst = stg + part * 8192 + (c8 >> 2) * 2048 + SWZ(row, c8 & 3); \
            const uint16_t* src = (part ? ksrc1 : ksrc0)                         \
                + (size_t)bh * TT * DH + (size_t)((kt_) * 64 + row) * DH + c8 * 8; \
            cp16s(sb + dst * 2, src);                                            \
        } else {                                                                 \
            int row = cid >> 3, c8 = cid & 7;                                    \
            unsigned dst = stg + 16384 + (part - 2) * 8192 + (c8 >> 2) * 4096 + SWZ(row, c8 & 3); \
            const uint16_t* src = (part == 2 ? vsrc0 : vsrc1)                    \
                + (size_t)bh * DH * TT + (size_t)row * TT + (kt_) * 64 + c8 * 8; \
            cp16s(sb + dst * 2, src);                                            \
        }                                                                        \
    }                                                                            \
} while (0)

    LOADKV(0, 0); CP_COMMIT();
    LOADKV(1, 1); CP_COMMIT();

    float m0s = -1e30f, m1s = -1e30f, l0s = 0.f, l1s = 0.f;
    float O[16][4];
#pragma unroll
    for (int i = 0; i < 16; i++)
#pragma unroll
        for (int j = 0; j < 4; j++) O[i][j] = 0.f;

    const int NT = TT / 64;   // 32 tiles
    for (int kt = 0; kt < NT; kt++) {
        const int buf = kt & 1;
        CP_WAIT(1);
        __syncthreads();

        const unsigned stgK = sb + (32768u + buf * 32768u) * 2;
        const unsigned stgV = stgK + 16384u * 2;

        // ---- scores: sacc[8][4] = Q . K^T over d=128 ----
        float sacc[8][4];
#pragma unroll
        for (int i = 0; i < 8; i++)
#pragma unroll
            for (int j = 0; j < 4; j++) sacc[i][j] = 0.f;

#pragma unroll
        for (int ks = 0; ks < 8; ks++) {
            const int kc = ks >> 1;
            const int c  = ((ks & 1) << 1) + (lane >> 4);
            unsigned ah[4], al[4], kh[4][4], kl[4][4];
            LDSM4(ah, sb + (0     + kc * 4096 + SWZ(warp * 16 + (lane & 15), c)) * 2);
            LDSM4(al, sb + (16384 + kc * 4096 + SWZ(warp * 16 + (lane & 15), c)) * 2);
#pragma unroll
            for (int nt = 0; nt < 4; nt++) {
                LDSM4(kh[nt], stgK + (kc * 2048 + SWZ(nt * 16 + (lane & 15), c)) * 2);
                LDSM4(kl[nt], stgK + (8192 + kc * 2048 + SWZ(nt * 16 + (lane & 15), c)) * 2);
            }
#pragma unroll
            for (int nt = 0; nt < 4; nt++)
#pragma unroll
                for (int sub = 0; sub < 2; sub++) {
                    int ni = nt * 2 + sub;
                    MMA_BF16(sacc[ni], ah, kh[nt][sub], kh[nt][sub + 2]);
                    MMA_BF16(sacc[ni], al, kh[nt][sub], kh[nt][sub + 2]);
                    MMA_BF16(sacc[ni], ah, kl[nt][sub], kl[nt][sub + 2]);
                }
        }

        // ---- online softmax (rows r = warp*16 + lane>>2 and +8) ----
        float tm0 = -1e30f, tm1 = -1e30f;
#pragma unroll
        for (int ni = 0; ni < 8; ni++) {
            tm0 = fmaxf(tm0, fmaxf(sacc[ni][0], sacc[ni][1]));
            tm1 = fmaxf(tm1, fmaxf(sacc[ni][2], sacc[ni][3]));
        }
        tm0 = fmaxf(tm0, __shfl_xor_sync(~0u, tm0, 1));
        tm0 = fmaxf(tm0, __shfl_xor_sync(~0u, tm0, 2));
        tm1 = fmaxf(tm1, __shfl_xor_sync(~0u, tm1, 1));
        tm1 = fmaxf(tm1, __shfl_xor_sync(~0u, tm1, 2));

        float mn0 = fmaxf(m0s, tm0), mn1 = fmaxf(m1s, tm1);
        float al0 = __expf(m0s - mn0), al1 = __expf(m1s - mn1);
        m0s = mn0; m1s = mn1;

        float rs0 = 0.f, rs1 = 0.f;
#pragma unroll
        for (int ni = 0; ni < 8; ni++) {
            sacc[ni][0] = __expf(sacc[ni][0] - mn0);
            sacc[ni][1] = __expf(sacc[ni][1] - mn0);
            sacc[ni][2] = __expf(sacc[ni][2] - mn1);
            sacc[ni][3] = __expf(sacc[ni][3] - mn1);
            rs0 += sacc[ni][0] + sacc[ni][1];
            rs1 += sacc[ni][2] + sacc[ni][3];
        }
        rs0 += __shfl_xor_sync(~0u, rs0, 1);
        rs0 += __shfl_xor_sync(~0u, rs0, 2);
        rs1 += __shfl_xor_sync(~0u, rs1, 1);
        rs1 += __shfl_xor_sync(~0u, rs1, 2);
        l0s = l0s * al0 + rs0;
        l1s = l1s * al1 + rs1;

#pragma unroll
        for (int dj = 0; dj < 16; dj++) {
            O[dj][0] *= al0; O[dj][1] *= al0;
            O[dj][2] *= al1; O[dj][3] *= al1;
        }

        // ---- PV: O += P(fp16, from regs) x V^T tiles ----
#pragma unroll
        for (int kt2 = 0; kt2 < 4; kt2++) {
            unsigned pa[4];
            pa[0] = h2u(__floats2half2_rn(sacc[kt2 * 2][0],     sacc[kt2 * 2][1]));
            pa[1] = h2u(__floats2half2_rn(sacc[kt2 * 2][2],     sacc[kt2 * 2][3]));
            pa[2] = h2u(__floats2half2_rn(sacc[kt2 * 2 + 1][0], sacc[kt2 * 2 + 1][1]));
            pa[3] = h2u(__floats2half2_rn(sacc[kt2 * 2 + 1][2], sacc[kt2 * 2 + 1][3]));
            const int kc = kt2 >> 1;
            const int c  = ((kt2 & 1) << 1) + (lane >> 4);
#pragma unroll
            for (int dt = 0; dt < 8; dt++) {
                unsigned vh[4], vl[4];
                LDSM4(vh, stgV + (kc * 4096 + SWZ(dt * 16 + (lane & 15), c)) * 2);
                LDSM4(vl, stgV + (8192 + kc * 4096 + SWZ(dt * 16 + (lane & 15), c)) * 2);
                MMA_F16(O[dt * 2],     pa, vh[0], vh[2]);
                MMA_F16(O[dt * 2 + 1], pa, vh[1], vh[3]);
                MMA_F16(O[dt * 2],     pa, vl[0], vl[2]);
                MMA_F16(O[dt * 2 + 1], pa, vl[1], vl[3]);
            }
        }

        __syncthreads();
        if (kt + 2 < NT) {
            LOADKV(kt + 2, buf);
            CP_COMMIT();
        }
    }
#undef LOADKV

    // ---- epilogue ----
    float inv0 = 1.f / l0s, inv1 = 1.f / l1s;
    int r = warp * 16 + (lane >> 2);
    float* o0 = out + (size_t)(b * TT + q0 + r) * 512 + kvh * 128;
    float* o1 = o0 + 8 * 512;
#pragma unroll
    for (int dj = 0; dj < 16; dj++) {
        int d = dj * 8 + ((lane & 3) << 1);
        *(float2*)(o0 + d) = make_float2(O[dj][0] * inv0, O[dj][1] * inv0);
        *(float2*)(o1 + d) = make_float2(O[dj][2] * inv1, O[dj][3] * inv1);
    }
}

// ---------------- launch ----------------
extern "C" void kernel_launch(void* const* d_in, const int* in_sizes, int n_in,
                              void* d_out, int out_size) {
    (void)in_sizes; (void)n_in; (void)out_size;
    const float* x = (const float*)d_in[0];
    const float* W = (const float*)d_in[1];
    const float* b = (const float*)d_in[2];
    float* out = (float*)d_out;

    const int SMEM_AB = 3 * 4 * 4096 * 2;   // 96KB
    cudaFuncSetAttribute(gemm_proj, cudaFuncAttributeMaxDynamicSharedMemorySize, SMEM_AB);
    cudaFuncSetAttribute(flash_attn, cudaFuncAttributeMaxDynamicSharedMemorySize, FL_SMEM);

    prep_x<<<16384, 256>>>(x);
    prep_w<<<9216, 256>>>(W, b);
    gemm_proj<<<dim3(9, 64), 256, SMEM_AB>>>(0);
    transpose_v<<<dim3(64, 4, 16), dim3(32, 8)>>>();
    flash_attn<<<dim3(16, 16), 256, FL_SMEM>>>(out);
}

// round 8
// speedup vs baseline: 5.8108x; 1.1275x over previous
#include <cuda_runtime.h>
#include <cuda_bf16.h>
#include <cuda_fp16.h>
#include <cstdint>
#include <math.h>

typedef __nv_bfloat16 bf16;

#define TT    2048
#define KDIM  2048
#define DH    128
#define NREDC 1152
#define MROWS 8192
#define NBH   16
#define SCALE 0.08838834764831845f   // 1/sqrt(128)

// ---------------- device scratch ----------------
__device__ bf16   g_xhi[(size_t)MROWS*KDIM];
__device__ bf16   g_xlo[(size_t)MROWS*KDIM];
__device__ bf16   g_whi[(size_t)NREDC*KDIM];
__device__ bf16   g_wlo[(size_t)NREDC*KDIM];
__device__ float  g_bred[NREDC];
__device__ bf16   g_qhi[(size_t)MROWS*DH];
__device__ bf16   g_qlo[(size_t)MROWS*DH];
__device__ bf16   g_khi[(size_t)NBH*TT*DH];
__device__ bf16   g_klo[(size_t)NBH*TT*DH];
__device__ __half g_v16[(size_t)NBH*TT*DH];    // V [bh][t][d], single fp16

// ---------------- helpers ----------------
__device__ __forceinline__ void split2(float v, bf16& h, bf16& l) {
    h = __float2bfloat16(v);
    l = __float2bfloat16(v - __bfloat162float(h));
}
__device__ __forceinline__ unsigned h2u(__half2 h) {
    return *reinterpret_cast<unsigned*>(&h);
}
__device__ __forceinline__ void cp16(void* sp, const void* gp) {
    unsigned s = (unsigned)__cvta_generic_to_shared(sp);
    asm volatile("cp.async.cg.shared.global [%0], [%1], 16;\n" :: "r"(s), "l"(gp));
}
__device__ __forceinline__ void cp16s(unsigned s, const void* gp) {
    asm volatile("cp.async.cg.shared.global [%0], [%1], 16;\n" :: "r"(s), "l"(gp));
}
#define CP_COMMIT() asm volatile("cp.async.commit_group;\n")
#define CP_WAIT(n)  asm volatile("cp.async.wait_group %0;\n" :: "n"(n))

// swizzled element offset inside an Nx32 16-bit tile (64B rows, 16B chunks)
#define SWZ(r, c) (((r) << 5) + ((((c) ^ (((r) >> 1) & 3))) << 3))

#define LDSM4(R, addr) \
    asm volatile("ldmatrix.sync.aligned.m8n8.x4.shared.b16 {%0,%1,%2,%3}, [%4];" \
        : "=r"((R)[0]), "=r"((R)[1]), "=r"((R)[2]), "=r"((R)[3]) : "r"(addr))

#define LDSM4T(R, addr) \
    asm volatile("ldmatrix.sync.aligned.m8n8.x4.trans.shared.b16 {%0,%1,%2,%3}, [%4];" \
        : "=r"((R)[0]), "=r"((R)[1]), "=r"((R)[2]), "=r"((R)[3]) : "r"(addr))

#define MMA_BF16(C, A, b0, b1) \
    asm volatile("mma.sync.aligned.m16n8k16.row.col.f32.bf16.bf16.f32 " \
        "{%0,%1,%2,%3},{%4,%5,%6,%7},{%8,%9},{%0,%1,%2,%3};" \
        : "+f"((C)[0]), "+f"((C)[1]), "+f"((C)[2]), "+f"((C)[3]) \
        : "r"((A)[0]), "r"((A)[1]), "r"((A)[2]), "r"((A)[3]), "r"(b0), "r"(b1))

#define MMA_F16(C, A, b0, b1) \
    asm volatile("mma.sync.aligned.m16n8k16.row.col.f32.f16.f16.f32 " \
        "{%0,%1,%2,%3},{%4,%5,%6,%7},{%8,%9},{%0,%1,%2,%3};" \
        : "+f"((C)[0]), "+f"((C)[1]), "+f"((C)[2]), "+f"((C)[3]) \
        : "r"((A)[0]), "r"((A)[1]), "r"((A)[2]), "r"((A)[3]), "r"(b0), "r"(b1))

// ---------------- prep ----------------
__global__ void prep_x(const float* __restrict__ x) {
    size_t i = ((size_t)blockIdx.x * 256 + threadIdx.x) * 4;
    float4 a = *(const float4*)(x + i);
    float arr[4] = {a.x, a.y, a.z, a.w};
#pragma unroll
    for (int j = 0; j < 4; j++) {
        bf16 h, l; split2(arr[j], h, l);
        g_xhi[i + j] = h;  g_xlo[i + j] = l;
    }
}

__global__ void prep_w(const float* __restrict__ W, const float* __restrict__ b) {
    int idx = blockIdx.x * 256 + threadIdx.x;
    int n = idx >> 11, c = idx & 2047;
    float v;
    if (n < 128) {
        v = 0.f;
#pragma unroll
        for (int h = 0; h < 16; h++) v += W[(size_t)(h * 128 + n) * KDIM + c];
        v *= SCALE;
    } else {
        v = W[(size_t)(n + 1920) * KDIM + c];
    }
    bf16 hh, ll; split2(v, hh, ll);
    g_whi[idx] = hh;  g_wlo[idx] = ll;

    if (idx < NREDC) {
        float bv;
        if (idx < 128) {
            bv = 0.f;
#pragma unroll
            for (int h = 0; h < 16; h++) bv += b[h * 128 + idx];
            bv *= SCALE;
        } else bv = b[idx + 1920];
        g_bred[idx] = bv;
    }
}

// ---------------- projection epilogue scatter ----------------
__device__ __forceinline__ void proj_store(int m, int n, float v0, float v1) {
    if (n < 128) {
        bf16 h0, l0, h1, l1;
        split2(v0, h0, l0);  split2(v1, h1, l1);
        size_t i = (size_t)m * DH + n;
        *(__nv_bfloat162*)&g_qhi[i] = __halves2bfloat162(h0, h1);
        *(__nv_bfloat162*)&g_qlo[i] = __halves2bfloat162(l0, l1);
    } else if (n < 640) {
        bf16 h0, l0, h1, l1;
        split2(v0, h0, l0);  split2(v1, h1, l1);
        int i2 = n - 128;
        int bh = ((m >> 11) << 2) + (i2 >> 7);
        size_t i = (size_t)bh * TT * DH + (size_t)(m & 2047) * DH + (i2 & 127);
        *(__nv_bfloat162*)&g_khi[i] = __halves2bfloat162(h0, h1);
        *(__nv_bfloat162*)&g_klo[i] = __halves2bfloat162(l0, l1);
    } else {
        int i2 = n - 640;
        int bh = ((m >> 11) << 2) + (i2 >> 7);
        size_t i = (size_t)bh * TT * DH + (size_t)(m & 2047) * DH + (i2 & 127);
        *(__half2*)&g_v16[i] = __floats2half2_rn(v0, v1);
    }
}

// ---------------- projection GEMM (bf16 3-product, 3-stage pipeline) ----------------
__global__ __launch_bounds__(256, 2)
void gemm_proj(int dummy) {
    extern __shared__ uint16_t sm[];
    constexpr int STAGE = 4 * 4096;

    const int tid  = threadIdx.x;
    const int lane = tid & 31;
    const int warp = tid >> 5;
    const int wm   = warp >> 2;
    const int wn   = warp & 3;
    const int m0   = blockIdx.y * 128;
    const int n0   = blockIdx.x * 128;

    const uint16_t* Ah = (const uint16_t*)g_xhi;
    const uint16_t* Al = (const uint16_t*)g_xlo;
    const uint16_t* Bh = (const uint16_t*)g_whi;
    const uint16_t* Bl = (const uint16_t*)g_wlo;
    const int KT = KDIM / 32;

    float acc[4][4][4];
#pragma unroll
    for (int mi = 0; mi < 4; mi++)
#pragma unroll
        for (int ni = 0; ni < 4; ni++)
#pragma unroll
            for (int r = 0; r < 4; r++) acc[mi][ni][r] = 0.f;

#define LOAD_STAGE(kt, buf) do {                                                \
    int k0_ = (kt) * 32;                                                        \
    uint16_t* st_ = sm + (buf) * STAGE;                                         \
    _Pragma("unroll")                                                           \
    for (int p = 0; p < 2; p++) {                                               \
        int id = tid + (p << 8);                                                \
        int row = id >> 2, c = id & 3;                                          \
        int so = SWZ(row, c);                                                   \
        size_t ga = (size_t)(m0 + row) * KDIM + k0_ + (c << 3);                 \
        size_t gb = (size_t)(n0 + row) * KDIM + k0_ + (c << 3);                 \
        cp16(st_ + so,         Ah + ga);                                        \
        cp16(st_ + 4096 + so,  Al + ga);                                        \
        cp16(st_ + 8192 + so,  Bh + gb);                                        \
        cp16(st_ + 12288 + so, Bl + gb);                                        \
    }                                                                           \
} while (0)

    LOAD_STAGE(0, 0); CP_COMMIT();
    LOAD_STAGE(1, 1); CP_COMMIT();

    int buf = 0;
    for (int kt = 0; kt < KT; kt++) {
        CP_WAIT(1);
        __syncthreads();
        if (kt + 2 < KT) {
            int nb = buf + 2; if (nb >= 3) nb -= 3;
            LOAD_STAGE(kt + 2, nb);
            CP_COMMIT();
        }

        const uint16_t* st = sm + buf * STAGE;
        unsigned base_a  = (unsigned)__cvta_generic_to_shared(st);
        unsigned base_al = base_a + 4096 * 2;
        unsigned base_bh = base_a + 8192 * 2;
        unsigned base_bl = base_a + 12288 * 2;

#pragma unroll
        for (int ks = 0; ks < 32; ks += 16) {
            unsigned Af[4][4], Bhf[2][4], Blf[2][4];
            const int chk = (ks >> 3) + (lane >> 4);
#pragma unroll
            for (int mi = 0; mi < 4; mi++) {
                int r = wm * 64 + mi * 16 + (lane & 15);
                LDSM4(Af[mi], base_a + SWZ(r, chk) * 2);
            }
#pragma unroll
            for (int bi = 0; bi < 2; bi++) {
                int r = wn * 32 + bi * 16 + (lane & 15);
                LDSM4(Bhf[bi], base_bh + SWZ(r, chk) * 2);
                LDSM4(Blf[bi], base_bl + SWZ(r, chk) * 2);
            }
#pragma unroll
            for (int mi = 0; mi < 4; mi++)
#pragma unroll
                for (int ni = 0; ni < 4; ni++) {
                    MMA_BF16(acc[mi][ni], Af[mi], Bhf[ni >> 1][ni & 1], Bhf[ni >> 1][(ni & 1) + 2]);
                    MMA_BF16(acc[mi][ni], Af[mi], Blf[ni >> 1][ni & 1], Blf[ni >> 1][(ni & 1) + 2]);
                }
#pragma unroll
            for (int mi = 0; mi < 4; mi++) {
                int r = wm * 64 + mi * 16 + (lane & 15);
                LDSM4(Af[mi], base_al + SWZ(r, chk) * 2);
            }
#pragma unroll
            for (int mi = 0; mi < 4; mi++)
#pragma unroll
                for (int ni = 0; ni < 4; ni++)
                    MMA_BF16(acc[mi][ni], Af[mi], Bhf[ni >> 1][ni & 1], Bhf[ni >> 1][(ni & 1) + 2]);
        }
        buf++; if (buf >= 3) buf = 0;
    }
#undef LOAD_STAGE

#pragma unroll
    for (int mi = 0; mi < 4; mi++)
#pragma unroll
        for (int ni = 0; ni < 4; ni++) {
            int mr = m0 + wm * 64 + mi * 16 + (lane >> 2);
            int nc = n0 + wn * 32 + ni * 8 + ((lane & 3) << 1);
            float* c = acc[mi][ni];
            float b0v = g_bred[nc], b1v = g_bred[nc + 1];
            proj_store(mr,     nc, c[0] + b0v, c[1] + b1v);
            proj_store(mr + 8, nc, c[2] + b0v, c[3] + b1v);
        }
}

// ---------------- fused flash attention ----------------
// CTA: 128 q rows x one bh. 8 warps; warp w owns q rows w*16..w*16+15.
// KV tiles of 64 keys, TRIPLE-buffered. Q resident in smem.
// smem (16-bit elems): Qhi[0,16384) Qlo[16384,32768)
//   stage s at 32768+s*24576: Khi[0,8192) Klo[8192,16384) V[16384,24576)
// K tiles [64 t][128 d] bf16 split; V tiles [64 t][128 d] fp16 single.
#define FL_STAGE 24576
#define FL_ELEMS (32768 + 3 * FL_STAGE)
#define FL_SMEM  (FL_ELEMS * 2)

__global__ __launch_bounds__(256)
void flash_attn(float* __restrict__ out) {
    extern __shared__ uint16_t fs[];
    const unsigned sb = (unsigned)__cvta_generic_to_shared(fs);

    const int tid  = threadIdx.x;
    const int lane = tid & 31;
    const int warp = tid >> 5;
    const int bh   = blockIdx.y;
    const int b    = bh >> 2;
    const int kvh  = bh & 3;
    const int q0   = blockIdx.x * 128;

    // ---- load Q (hi+lo) ----
    {
        const uint16_t* qsrc0 = (const uint16_t*)g_qhi;
        const uint16_t* qsrc1 = (const uint16_t*)g_qlo;
#pragma unroll
        for (int p = 0; p < 16; p++) {
            int id = tid + (p << 8);
            int part = id >> 11, cid = id & 2047;
            int row = cid >> 4, c8 = cid & 15;
            unsigned dst = (unsigned)(part * 16384 + (c8 >> 2) * 4096 + SWZ(row, c8 & 3));
            const uint16_t* src = (part ? qsrc1 : qsrc0) + (size_t)(b * TT + q0 + row) * DH + c8 * 8;
            cp16s(sb + dst * 2, src);
        }
    }
    CP_COMMIT();

#define LOADKV(kt_, buf_) do {                                                   \
    const uint16_t* ksrc0 = (const uint16_t*)g_khi;                              \
    const uint16_t* ksrc1 = (const uint16_t*)g_klo;                              \
    const uint16_t* vsrc  = (const uint16_t*)g_v16;                              \
    unsigned stg = 32768u + (buf_) * (unsigned)FL_STAGE;                         \
    _Pragma("unroll")                                                            \
    for (int p = 0; p < 12; p++) {                                               \
        int id = tid + (p << 8);                                                 \
        int part = id >> 10, cid = id & 1023;                                    \
        int row = cid >> 4, c8 = cid & 15;                                       \
        unsigned dst = stg + part * 8192 + (c8 >> 2) * 2048 + SWZ(row, c8 & 3);  \
        const uint16_t* src = (part == 0 ? ksrc0 : (part == 1 ? ksrc1 : vsrc))   \
            + (size_t)bh * TT * DH + (size_t)((kt_) * 64 + row) * DH + c8 * 8;   \
        cp16s(sb + dst * 2, src);                                                \
    }                                                                            \
} while (0)

    LOADKV(0, 0); CP_COMMIT();
    LOADKV(1, 1); CP_COMMIT();

    float m0s = -1e30f, m1s = -1e30f, l0s = 0.f, l1s = 0.f;
    float O[16][4];
#pragma unroll
    for (int i = 0; i < 16; i++)
#pragma unroll
        for (int j = 0; j < 4; j++) O[i][j] = 0.f;

    const int NT = TT / 64;   // 32 tiles
    int buf = 0;
    for (int kt = 0; kt < NT; kt++) {
        CP_WAIT(1);
        __syncthreads();
        if (kt + 2 < NT) {
            int nb = buf + 2; if (nb >= 3) nb -= 3;
            LOADKV(kt + 2, nb);
            CP_COMMIT();
        }

        const unsigned stgK = sb + (32768u + buf * (unsigned)FL_STAGE) * 2;
        const unsigned stgV = stgK + 16384u * 2;

        // ---- scores: sacc[8][4] = Q . K^T over d=128 ----
        float sacc[8][4];
#pragma unroll
        for (int i = 0; i < 8; i++)
#pragma unroll
            for (int j = 0; j < 4; j++) sacc[i][j] = 0.f;

#pragma unroll
        for (int ks = 0; ks < 8; ks++) {
            const int kc = ks >> 1;
            const int c  = ((ks & 1) << 1) + (lane >> 4);
            unsigned ah[4], al[4], kh[4][4], kl[4][4];
            LDSM4(ah, sb + (0     + kc * 4096 + SWZ(warp * 16 + (lane & 15), c)) * 2);
            LDSM4(al, sb + (16384 + kc * 4096 + SWZ(warp * 16 + (lane & 15), c)) * 2);
#pragma unroll
            for (int nt = 0; nt < 4; nt++) {
                LDSM4(kh[nt], stgK + (kc * 2048 + SWZ(nt * 16 + (lane & 15), c)) * 2);
                LDSM4(kl[nt], stgK + (8192 + kc * 2048 + SWZ(nt * 16 + (lane & 15), c)) * 2);
            }
#pragma unroll
            for (int nt = 0; nt < 4; nt++)
#pragma unroll
                for (int sub = 0; sub < 2; sub++) {
                    int ni = nt * 2 + sub;
                    MMA_BF16(sacc[ni], ah, kh[nt][sub], kh[nt][sub + 2]);
                    MMA_BF16(sacc[ni], al, kh[nt][sub], kh[nt][sub + 2]);
                    MMA_BF16(sacc[ni], ah, kl[nt][sub], kl[nt][sub + 2]);
                }
        }

        // ---- online softmax ----
        float tm0 = -1e30f, tm1 = -1e30f;
#pragma unroll
        for (int ni = 0; ni < 8; ni++) {
            tm0 = fmaxf(tm0, fmaxf(sacc[ni][0], sacc[ni][1]));
            tm1 = fmaxf(tm1, fmaxf(sacc[ni][2], sacc[ni][3]));
        }
        tm0 = fmaxf(tm0, __shfl_xor_sync(~0u, tm0, 1));
        tm0 = fmaxf(tm0, __shfl_xor_sync(~0u, tm0, 2));
        tm1 = fmaxf(tm1, __shfl_xor_sync(~0u, tm1, 1));
        tm1 = fmaxf(tm1, __shfl_xor_sync(~0u, tm1, 2));

        float mn0 = fmaxf(m0s, tm0), mn1 = fmaxf(m1s, tm1);
        float al0 = __expf(m0s - mn0), al1 = __expf(m1s - mn1);
        m0s = mn0; m1s = mn1;

        float rs0 = 0.f, rs1 = 0.f;
#pragma unroll
        for (int ni = 0; ni < 8; ni++) {
            sacc[ni][0] = __expf(sacc[ni][0] - mn0);
            sacc[ni][1] = __expf(sacc[ni][1] - mn0);
            sacc[ni][2] = __expf(sacc[ni][2] - mn1);
            sacc[ni][3] = __expf(sacc[ni][3] - mn1);
            rs0 += sacc[ni][0] + sacc[ni][1];
            rs1 += sacc[ni][2] + sacc[ni][3];
        }
        rs0 += __shfl_xor_sync(~0u, rs0, 1);
        rs0 += __shfl_xor_sync(~0u, rs0, 2);
        rs1 += __shfl_xor_sync(~0u, rs1, 1);
        rs1 += __shfl_xor_sync(~0u, rs1, 2);
        l0s = l0s * al0 + rs0;
        l1s = l1s * al1 + rs1;

#pragma unroll
        for (int dj = 0; dj < 16; dj++) {
            O[dj][0] *= al0; O[dj][1] *= al0;
            O[dj][2] *= al1; O[dj][3] *= al1;
        }

        // ---- PV: O += P(fp16 regs) x V (trans-ldmatrix from [t][d]) ----
#pragma unroll
        for (int kt2 = 0; kt2 < 4; kt2++) {
            unsigned pa[4];
            pa[0] = h2u(__floats2half2_rn(sacc[kt2 * 2][0],     sacc[kt2 * 2][1]));
            pa[1] = h2u(__floats2half2_rn(sacc[kt2 * 2][2],     sacc[kt2 * 2][3]));
            pa[2] = h2u(__floats2half2_rn(sacc[kt2 * 2 + 1][0], sacc[kt2 * 2 + 1][1]));
            pa[3] = h2u(__floats2half2_rn(sacc[kt2 * 2 + 1][2], sacc[kt2 * 2 + 1][3]));
#pragma unroll
            for (int dt = 0; dt < 8; dt++) {
                unsigned v[4];
                const int chunk = dt >> 1;
                const int c = ((dt & 1) << 1) + (lane >> 4);
                LDSM4T(v, stgV + (chunk * 2048 + SWZ(kt2 * 16 + (lane & 15), c)) * 2);
                MMA_F16(O[dt * 2],     pa, v[0], v[1]);
                MMA_F16(O[dt * 2 + 1], pa, v[2], v[3]);
            }
        }

        buf++; if (buf >= 3) buf = 0;
    }
#undef LOADKV

    // ---- epilogue ----
    float inv0 = 1.f / l0s, inv1 = 1.f / l1s;
    int r = warp * 16 + (lane >> 2);
    float* o0 = out + (size_t)(b * TT + q0 + r) * 512 + kvh * 128;
    float* o1 = o0 + 8 * 512;
#pragma unroll
    for (int dj = 0; dj < 16; dj++) {
        int d = dj * 8 + ((lane & 3) << 1);
        *(float2*)(o0 + d) = make_float2(O[dj][0] * inv0, O[dj][1] * inv0);
        *(float2*)(o1 + d) = make_float2(O[dj][2] * inv1, O[dj][3] * inv1);
    }
}

// ---------------- launch ----------------
extern "C" void kernel_launch(void* const* d_in, const int* in_sizes, int n_in,
                              void* d_out, int out_size) {
    (void)in_sizes; (void)n_in; (void)out_size;
    const float* x = (const float*)d_in[0];
    const float* W = (const float*)d_in[1];
    const float* b = (const float*)d_in[2];
    float* out = (float*)d_out;

    const int SMEM_AB = 3 * 4 * 4096 * 2;   // 96KB
    cudaFuncSetAttribute(gemm_proj, cudaFuncAttributeMaxDynamicSharedMemorySize, SMEM_AB);
    cudaFuncSetAttribute(flash_attn, cudaFuncAttributeMaxDynamicSharedMemorySize, FL_SMEM);

    prep_x<<<16384, 256>>>(x);
    prep_w<<<9216, 256>>>(W, b);
    gemm_proj<<<dim3(9, 64), 256, SMEM_AB>>>(0);
    flash_attn<<<dim3(16, 16), 256, FL_SMEM>>>(out);
}